// round 14
// baseline (speedup 1.0000x reference)
#include <cuda_runtime.h>
#include <math.h>

#define NT   2048      // tokens (2*1024)
#define NH   2048      // hidden
#define NE   64        // experts
#define NK   6         // top_k
#define NF   768       // moe intermediate
#define NG   8         // groups
#define EPG  8         // experts per group
#define NKG  4         // topk groups
#define NCAP 384       // capacity per expert
#define RSCALE 2.5f

// ---------------- scratch (device globals; no allocation allowed) ----------
__device__ float g_logits[NT * NE];
__device__ int   g_cnt[NE];
__device__ int   g_tok[NE * NCAP];
__device__ float g_wgt[NE * NCAP];
__device__ float g_hbuf[(size_t)NE * NCAP * NF];   // 75.5 MB
__device__ float g_sbuf[(size_t)NT * NF];          // 6.3 MB

// ---------------------------------------------------------------------------
__global__ void zero_cnt_kernel() {
    int i = threadIdx.x;
    if (i < NE) g_cnt[i] = 0;
}

// ---------------- router logits: X[NT,NH] @ gate_w[NH,NE] -> g_logits ------
__global__ void router_gemm(const float* __restrict__ X,
                            const float* __restrict__ Wg) {
    __shared__ __align__(16) float As[64][16];
    __shared__ __align__(16) float Bs[16][64];
    int bm = blockIdx.x * 64;
    int tid = threadIdx.x;
    int tx = tid & 15, ty = tid >> 4;
    int arow = tid >> 2, akg = tid & 3;
    int brow = tid >> 4, bng = tid & 15;
    float acc[4][4] = {};
    for (int k0 = 0; k0 < NH; k0 += 16) {
        *(float4*)&As[arow][akg * 4] =
            *(const float4*)&X[(size_t)(bm + arow) * NH + k0 + akg * 4];
        *(float4*)&Bs[brow][bng * 4] =
            *(const float4*)&Wg[(size_t)(k0 + brow) * NE + bng * 4];
        __syncthreads();
#pragma unroll
        for (int kk = 0; kk < 16; kk++) {
            float4 b4 = *(const float4*)&Bs[kk][tx * 4];
            float a[4];
#pragma unroll
            for (int i = 0; i < 4; i++) a[i] = As[ty * 4 + i][kk];
#pragma unroll
            for (int i = 0; i < 4; i++) {
                acc[i][0] += a[i] * b4.x;
                acc[i][1] += a[i] * b4.y;
                acc[i][2] += a[i] * b4.z;
                acc[i][3] += a[i] * b4.w;
            }
        }
        __syncthreads();
    }
#pragma unroll
    for (int i = 0; i < 4; i++)
#pragma unroll
        for (int j = 0; j < 4; j++)
            g_logits[(size_t)(bm + ty * 4 + i) * NE + tx * 4 + j] = acc[i][j];
}

// ---------------- grouped top-k routing + scatter ---------------------------
__global__ void topk_route(const float* __restrict__ bias) {
    int t = blockIdx.x * blockDim.x + threadIdx.x;
    if (t >= NT) return;
    float s[NE], sb[NE];
#pragma unroll 8
    for (int e = 0; e < NE; e++) {
        float l = g_logits[(size_t)t * NE + e];
        float sv = 1.f / (1.f + expf(-l));
        s[e] = sv;
        sb[e] = sv + bias[e];
    }
    // group scores = sum of top-2 biased scores per group
    float gsc[NG];
#pragma unroll
    for (int g = 0; g < NG; g++) {
        float m1 = -INFINITY, m2 = -INFINITY;
#pragma unroll
        for (int j = 0; j < EPG; j++) {
            float v = sb[g * EPG + j];
            if (v > m1) { m2 = m1; m1 = v; }
            else if (v > m2) { m2 = v; }
        }
        gsc[g] = m1 + m2;
    }
    // top-NKG groups (ties -> lowest index, matching jax top_k)
    bool gsel[NG];
#pragma unroll
    for (int g = 0; g < NG; g++) gsel[g] = false;
    for (int r = 0; r < NKG; r++) {
        int bi = 0; float bv = -INFINITY;
        for (int g = 0; g < NG; g++)
            if (!gsel[g] && gsc[g] > bv) { bv = gsc[g]; bi = g; }
        gsel[bi] = true;
    }
    // top-NK experts within selected groups by biased score
    bool used[NE];
#pragma unroll
    for (int e = 0; e < NE; e++) used[e] = false;
    int ids[NK];
    float ws[NK];
    float wsum = 0.f;
    for (int r = 0; r < NK; r++) {
        int bi = 0; float bv = -INFINITY;
        for (int e = 0; e < NE; e++) {
            if (used[e] || !gsel[e / EPG]) continue;
            if (sb[e] > bv) { bv = sb[e]; bi = e; }
        }
        used[bi] = true;
        ids[r] = bi;
        ws[r] = s[bi];   // weights come from UNBIASED scores
        wsum += s[bi];
    }
    float inv = RSCALE / wsum;
    for (int r = 0; r < NK; r++) {
        int e = ids[r];
        int slot = atomicAdd(&g_cnt[e], 1);
        if (slot < NCAP) {
            g_tok[e * NCAP + slot] = t;
            g_wgt[e * NCAP + slot] = ws[r] * inv;
        }
    }
}

// ---------------- grouped SwiGLU GEMM1: hbuf = silu(Xe@Wg) * (Xe@Wu) --------
__global__ void moe_gemm1(const float* __restrict__ X,
                          const float* __restrict__ Wg,
                          const float* __restrict__ Wu) {
    int e = blockIdx.z;
    int cnt = g_cnt[e]; if (cnt > NCAP) cnt = NCAP;
    int row0 = blockIdx.y * 64;
    if (row0 >= cnt) return;
    int n0 = blockIdx.x * 64;

    __shared__ __align__(16) float As[64][16];
    __shared__ __align__(16) float Bg[16][64];
    __shared__ __align__(16) float Bu[16][64];
    __shared__ int toks[64];

    int tid = threadIdx.x;
    if (tid < 64) {
        int r = row0 + tid;
        toks[tid] = (r < cnt) ? g_tok[e * NCAP + r] : 0;
    }
    __syncthreads();

    int tx = tid & 15, ty = tid >> 4;
    int arow = tid >> 2, akg = tid & 3;
    int brow = tid >> 4, bng = tid & 15;
    const float* wg = Wg + (size_t)e * NH * NF;
    const float* wu = Wu + (size_t)e * NH * NF;
    float ag[4][4] = {}, au[4][4] = {};

    for (int k0 = 0; k0 < NH; k0 += 16) {
        *(float4*)&As[arow][akg * 4] =
            *(const float4*)&X[(size_t)toks[arow] * NH + k0 + akg * 4];
        *(float4*)&Bg[brow][bng * 4] =
            *(const float4*)&wg[(size_t)(k0 + brow) * NF + n0 + bng * 4];
        *(float4*)&Bu[brow][bng * 4] =
            *(const float4*)&wu[(size_t)(k0 + brow) * NF + n0 + bng * 4];
        __syncthreads();
#pragma unroll
        for (int kk = 0; kk < 16; kk++) {
            float4 bg4 = *(const float4*)&Bg[kk][tx * 4];
            float4 bu4 = *(const float4*)&Bu[kk][tx * 4];
            float a[4];
#pragma unroll
            for (int i = 0; i < 4; i++) a[i] = As[ty * 4 + i][kk];
#pragma unroll
            for (int i = 0; i < 4; i++) {
                ag[i][0] += a[i] * bg4.x; ag[i][1] += a[i] * bg4.y;
                ag[i][2] += a[i] * bg4.z; ag[i][3] += a[i] * bg4.w;
                au[i][0] += a[i] * bu4.x; au[i][1] += a[i] * bu4.y;
                au[i][2] += a[i] * bu4.z; au[i][3] += a[i] * bu4.w;
            }
        }
        __syncthreads();
    }

    float* hb = g_hbuf + (size_t)e * NCAP * NF;
#pragma unroll
    for (int i = 0; i < 4; i++) {
        int r = row0 + ty * 4 + i;
        if (r >= cnt) continue;
#pragma unroll
        for (int j = 0; j < 4; j++) {
            float g = ag[i][j];
            float h = (g / (1.f + expf(-g))) * au[i][j];
            hb[(size_t)r * NF + n0 + tx * 4 + j] = h;
        }
    }
}

// ---------------- grouped down GEMM: out += w * (hbuf @ Wd) -----------------
__global__ void moe_gemm2(const float* __restrict__ Wd,
                          float* __restrict__ out) {
    int e = blockIdx.z;
    int cnt = g_cnt[e]; if (cnt > NCAP) cnt = NCAP;
    int row0 = blockIdx.y * 64;
    if (row0 >= cnt) return;
    int n0 = blockIdx.x * 64;

    __shared__ __align__(16) float As[64][16];
    __shared__ __align__(16) float Bs[16][64];

    const float* hb = g_hbuf + (size_t)e * NCAP * NF;
    const float* wd = Wd + (size_t)e * NF * NH;

    int tid = threadIdx.x;
    int tx = tid & 15, ty = tid >> 4;
    int arow = tid >> 2, akg = tid & 3;
    int brow = tid >> 4, bng = tid & 15;
    float acc[4][4] = {};

    for (int k0 = 0; k0 < NF; k0 += 16) {
        *(float4*)&As[arow][akg * 4] =
            *(const float4*)&hb[(size_t)(row0 + arow) * NF + k0 + akg * 4];
        *(float4*)&Bs[brow][bng * 4] =
            *(const float4*)&wd[(size_t)(k0 + brow) * NH + n0 + bng * 4];
        __syncthreads();
#pragma unroll
        for (int kk = 0; kk < 16; kk++) {
            float4 b4 = *(const float4*)&Bs[kk][tx * 4];
            float a[4];
#pragma unroll
            for (int i = 0; i < 4; i++) a[i] = As[ty * 4 + i][kk];
#pragma unroll
            for (int i = 0; i < 4; i++) {
                acc[i][0] += a[i] * b4.x; acc[i][1] += a[i] * b4.y;
                acc[i][2] += a[i] * b4.z; acc[i][3] += a[i] * b4.w;
            }
        }
        __syncthreads();
    }

#pragma unroll
    for (int i = 0; i < 4; i++) {
        int r = row0 + ty * 4 + i;
        if (r >= cnt) continue;
        int tok = g_tok[e * NCAP + r];
        float w = g_wgt[e * NCAP + r];
        float* op = out + (size_t)tok * NH + n0 + tx * 4;
#pragma unroll
        for (int j = 0; j < 4; j++)
            atomicAdd(op + j, acc[i][j] * w);
    }
}

// ---------------- shared expert GEMM1: sbuf = silu(X@Wg)*(X@Wu) -------------
__global__ void shared_gemm1(const float* __restrict__ X,
                             const float* __restrict__ Wg,
                             const float* __restrict__ Wu) {
    int row0 = blockIdx.y * 64;
    int n0 = blockIdx.x * 64;

    __shared__ __align__(16) float As[64][16];
    __shared__ __align__(16) float Bg[16][64];
    __shared__ __align__(16) float Bu[16][64];

    int tid = threadIdx.x;
    int tx = tid & 15, ty = tid >> 4;
    int arow = tid >> 2, akg = tid & 3;
    int brow = tid >> 4, bng = tid & 15;
    float ag[4][4] = {}, au[4][4] = {};

    for (int k0 = 0; k0 < NH; k0 += 16) {
        *(float4*)&As[arow][akg * 4] =
            *(const float4*)&X[(size_t)(row0 + arow) * NH + k0 + akg * 4];
        *(float4*)&Bg[brow][bng * 4] =
            *(const float4*)&Wg[(size_t)(k0 + brow) * NF + n0 + bng * 4];
        *(float4*)&Bu[brow][bng * 4] =
            *(const float4*)&Wu[(size_t)(k0 + brow) * NF + n0 + bng * 4];
        __syncthreads();
#pragma unroll
        for (int kk = 0; kk < 16; kk++) {
            float4 bg4 = *(const float4*)&Bg[kk][tx * 4];
            float4 bu4 = *(const float4*)&Bu[kk][tx * 4];
            float a[4];
#pragma unroll
            for (int i = 0; i < 4; i++) a[i] = As[ty * 4 + i][kk];
#pragma unroll
            for (int i = 0; i < 4; i++) {
                ag[i][0] += a[i] * bg4.x; ag[i][1] += a[i] * bg4.y;
                ag[i][2] += a[i] * bg4.z; ag[i][3] += a[i] * bg4.w;
                au[i][0] += a[i] * bu4.x; au[i][1] += a[i] * bu4.y;
                au[i][2] += a[i] * bu4.z; au[i][3] += a[i] * bu4.w;
            }
        }
        __syncthreads();
    }

#pragma unroll
    for (int i = 0; i < 4; i++) {
        int r = row0 + ty * 4 + i;
#pragma unroll
        for (int j = 0; j < 4; j++) {
            float g = ag[i][j];
            float h = (g / (1.f + expf(-g))) * au[i][j];
            g_sbuf[(size_t)r * NF + n0 + tx * 4 + j] = h;
        }
    }
}

// ---------------- shared expert GEMM2: out = sbuf @ Wd (plain store) --------
__global__ void shared_gemm2(const float* __restrict__ Wd,
                             float* __restrict__ out) {
    int row0 = blockIdx.y * 64;
    int n0 = blockIdx.x * 64;

    __shared__ __align__(16) float As[64][16];
    __shared__ __align__(16) float Bs[16][64];

    int tid = threadIdx.x;
    int tx = tid & 15, ty = tid >> 4;
    int arow = tid >> 2, akg = tid & 3;
    int brow = tid >> 4, bng = tid & 15;
    float acc[4][4] = {};

    for (int k0 = 0; k0 < NF; k0 += 16) {
        *(float4*)&As[arow][akg * 4] =
            *(const float4*)&g_sbuf[(size_t)(row0 + arow) * NF + k0 + akg * 4];
        *(float4*)&Bs[brow][bng * 4] =
            *(const float4*)&Wd[(size_t)(k0 + brow) * NH + n0 + bng * 4];
        __syncthreads();
#pragma unroll
        for (int kk = 0; kk < 16; kk++) {
            float4 b4 = *(const float4*)&Bs[kk][tx * 4];
            float a[4];
#pragma unroll
            for (int i = 0; i < 4; i++) a[i] = As[ty * 4 + i][kk];
#pragma unroll
            for (int i = 0; i < 4; i++) {
                acc[i][0] += a[i] * b4.x; acc[i][1] += a[i] * b4.y;
                acc[i][2] += a[i] * b4.z; acc[i][3] += a[i] * b4.w;
            }
        }
        __syncthreads();
    }

#pragma unroll
    for (int i = 0; i < 4; i++) {
        int r = row0 + ty * 4 + i;
#pragma unroll
        for (int j = 0; j < 4; j++)
            out[(size_t)r * NH + n0 + tx * 4 + j] = acc[i][j];
    }
}

// ---------------------------------------------------------------------------
extern "C" void kernel_launch(void* const* d_in, const int* in_sizes, int n_in,
                              void* d_out, int out_size) {
    const float* x       = (const float*)d_in[0];
    const float* gate_w  = (const float*)d_in[1];
    const float* bias    = (const float*)d_in[2];
    const float* w_gate  = (const float*)d_in[3];
    const float* w_up    = (const float*)d_in[4];
    const float* w_down  = (const float*)d_in[5];
    const float* ws_gate = (const float*)d_in[6];
    const float* ws_up   = (const float*)d_in[7];
    const float* ws_down = (const float*)d_in[8];
    float* out = (float*)d_out;

    zero_cnt_kernel<<<1, 64>>>();
    router_gemm<<<NT / 64, 256>>>(x, gate_w);
    topk_route<<<NT / 256, 256>>>(bias);

    // shared expert first: plain stores initialize the (poisoned) output
    shared_gemm1<<<dim3(NF / 64, NT / 64), 256>>>(x, ws_gate, ws_up);
    shared_gemm2<<<dim3(NH / 64, NT / 64), 256>>>(ws_down, out);

    // routed experts: grouped GEMMs, weighted atomic accumulation into out
    moe_gemm1<<<dim3(NF / 64, NCAP / 64, NE), 256>>>(x, w_gate, w_up);
    moe_gemm2<<<dim3(NH / 64, NCAP / 64, NE), 256>>>(w_down, out);
}

// round 15
// speedup vs baseline: 1.1263x; 1.1263x over previous
#include <cuda_runtime.h>
#include <math.h>

#define NT   2048      // tokens (2*1024)
#define NH   2048      // hidden
#define NE   64        // experts
#define NK   6         // top_k
#define NF   768       // moe intermediate
#define NG   8         // groups
#define EPG  8         // experts per group
#define NKG  4         // topk groups
#define NCAP 384       // capacity per expert
#define RSCALE 2.5f

typedef unsigned long long ull;

// ---------------- scratch (device globals; no allocation allowed) ----------
__device__ float g_logits[NT * NE];
__device__ int   g_cnt[NE];
__device__ int   g_tok[NE * NCAP];
__device__ float g_wgt[NE * NCAP];
__device__ float g_hbuf[(size_t)NE * NCAP * NF];   // 75.5 MB
__device__ float g_sbuf[(size_t)NT * NF];          // 6.3 MB

// ---------------- f32x2 packed-math helpers --------------------------------
__device__ __forceinline__ ull dup2(float x) {
    ull r; unsigned xi = __float_as_uint(x);
    asm("mov.b64 %0, {%1, %1};" : "=l"(r) : "r"(xi));
    return r;
}
__device__ __forceinline__ void ffma2(ull& d, ull a, ull b) {
    asm("fma.rn.f32x2 %0, %1, %2, %0;" : "+l"(d) : "l"(a), "l"(b));
}
__device__ __forceinline__ float2 unpk(ull v) {
    float2 f;
    asm("mov.b64 {%0, %1}, %2;" : "=f"(f.x), "=f"(f.y) : "l"(v));
    return f;
}
__device__ __forceinline__ float silu(float g) {
    return g / (1.f + expf(-g));
}

// ---------------------------------------------------------------------------
__global__ void zero_cnt_kernel() {
    int i = threadIdx.x;
    if (i < NE) g_cnt[i] = 0;
}

// ---------------- router logits: X[NT,NH] @ gate_w[NH,NE] -> g_logits ------
__global__ void router_gemm(const float* __restrict__ X,
                            const float* __restrict__ Wg) {
    __shared__ __align__(16) float As[64][16];
    __shared__ __align__(16) float Bs[16][64];
    int bm = blockIdx.x * 64;
    int tid = threadIdx.x;
    int tx = tid & 15, ty = tid >> 4;
    int arow = tid >> 2, akg = tid & 3;
    int brow = tid >> 4, bng = tid & 15;
    float acc[4][4] = {};
    for (int k0 = 0; k0 < NH; k0 += 16) {
        *(float4*)&As[arow][akg * 4] =
            *(const float4*)&X[(size_t)(bm + arow) * NH + k0 + akg * 4];
        *(float4*)&Bs[brow][bng * 4] =
            *(const float4*)&Wg[(size_t)(k0 + brow) * NE + bng * 4];
        __syncthreads();
#pragma unroll
        for (int kk = 0; kk < 16; kk++) {
            float4 b4 = *(const float4*)&Bs[kk][tx * 4];
            float a[4];
#pragma unroll
            for (int i = 0; i < 4; i++) a[i] = As[ty * 4 + i][kk];
#pragma unroll
            for (int i = 0; i < 4; i++) {
                acc[i][0] += a[i] * b4.x;
                acc[i][1] += a[i] * b4.y;
                acc[i][2] += a[i] * b4.z;
                acc[i][3] += a[i] * b4.w;
            }
        }
        __syncthreads();
    }
#pragma unroll
    for (int i = 0; i < 4; i++)
#pragma unroll
        for (int j = 0; j < 4; j++)
            g_logits[(size_t)(bm + ty * 4 + i) * NE + tx * 4 + j] = acc[i][j];
}

// ---------------- grouped top-k routing + scatter ---------------------------
__global__ void topk_route(const float* __restrict__ bias) {
    int t = blockIdx.x * blockDim.x + threadIdx.x;
    if (t >= NT) return;
    float s[NE], sb[NE];
#pragma unroll 8
    for (int e = 0; e < NE; e++) {
        float l = g_logits[(size_t)t * NE + e];
        float sv = 1.f / (1.f + expf(-l));
        s[e] = sv;
        sb[e] = sv + bias[e];
    }
    float gsc[NG];
#pragma unroll
    for (int g = 0; g < NG; g++) {
        float m1 = -INFINITY, m2 = -INFINITY;
#pragma unroll
        for (int j = 0; j < EPG; j++) {
            float v = sb[g * EPG + j];
            if (v > m1) { m2 = m1; m1 = v; }
            else if (v > m2) { m2 = v; }
        }
        gsc[g] = m1 + m2;
    }
    bool gsel[NG];
#pragma unroll
    for (int g = 0; g < NG; g++) gsel[g] = false;
    for (int r = 0; r < NKG; r++) {
        int bi = 0; float bv = -INFINITY;
        for (int g = 0; g < NG; g++)
            if (!gsel[g] && gsc[g] > bv) { bv = gsc[g]; bi = g; }
        gsel[bi] = true;
    }
    bool used[NE];
#pragma unroll
    for (int e = 0; e < NE; e++) used[e] = false;
    int ids[NK];
    float ws[NK];
    float wsum = 0.f;
    for (int r = 0; r < NK; r++) {
        int bi = 0; float bv = -INFINITY;
        for (int e = 0; e < NE; e++) {
            if (used[e] || !gsel[e / EPG]) continue;
            if (sb[e] > bv) { bv = sb[e]; bi = e; }
        }
        used[bi] = true;
        ids[r] = bi;
        ws[r] = s[bi];
        wsum += s[bi];
    }
    float inv = RSCALE / wsum;
    for (int r = 0; r < NK; r++) {
        int e = ids[r];
        int slot = atomicAdd(&g_cnt[e], 1);
        if (slot < NCAP) {
            g_tok[e * NCAP + slot] = t;
            g_wgt[e * NCAP + slot] = ws[r] * inv;
        }
    }
}

// ============================================================================
// GEMM1-type: C_gate/C_up = A[128,K] @ {Bg,Bu}[K,64]; epilogue silu(g)*u.
// CTA tile 128(M) x 64(N), K-panel 16, double-buffered, f32x2 math.
// Per thread (256 thr): 8(M) x 4(N) outputs per matrix, pairs packed along M.
// ============================================================================

// ---------------- routed SwiGLU GEMM1: hbuf = silu(Xe@Wg) * (Xe@Wu) ---------
__global__ __launch_bounds__(256) void moe_gemm1(const float* __restrict__ X,
                                                 const float* __restrict__ Wg,
                                                 const float* __restrict__ Wu) {
    int e = blockIdx.z;
    int cnt = g_cnt[e]; if (cnt > NCAP) cnt = NCAP;
    int row0 = blockIdx.y * 128;
    if (row0 >= cnt) return;
    int nblk = blockIdx.x * 64;

    __shared__ __align__(16) float As[2][16][128];
    __shared__ __align__(16) float Bg[2][16][64];
    __shared__ __align__(16) float Bu[2][16][64];
    __shared__ int stok[128];

    int tid = threadIdx.x;
    if (tid < 128) {
        int r = row0 + tid;
        stok[tid] = (r < cnt) ? g_tok[e * NCAP + r] : 0;
    }
    __syncthreads();

    // global load assignments
    int am = tid >> 1, akq = tid & 1;                  // A: row am, k-quad akq
    int bk = tid >> 4, bn = (tid & 15) * 4;            // B: row bk, 4 cols
    const float* aptr = X + (size_t)stok[am] * NH + akq * 8;
    const float* wgp = Wg + (size_t)e * NH * NF + (size_t)bk * NF + nblk + bn;
    const float* wup = Wu + (size_t)e * NH * NF + (size_t)bk * NF + nblk + bn;

    // compute fragment mapping
    int w = tid >> 5, lane = tid & 31;
    int m0 = w * 16 + (lane & 1) * 8;                  // 8 rows
    int ln2 = (lane >> 1) * 2;                          // cols ln2,ln2+1,+32,+33

    float4 sa0, sa1, sbg, sbu;
    sa0 = *(const float4*)(aptr);
    sa1 = *(const float4*)(aptr + 4);
    sbg = *(const float4*)(wgp);
    sbu = *(const float4*)(wup);
#pragma unroll
    for (int j = 0; j < 4; j++) As[0][akq * 8 + j][am] = ((const float*)&sa0)[j];
#pragma unroll
    for (int j = 0; j < 4; j++) As[0][akq * 8 + 4 + j][am] = ((const float*)&sa1)[j];
    *(float4*)&Bg[0][bk][bn] = sbg;
    *(float4*)&Bu[0][bk][bn] = sbu;
    __syncthreads();

    ull ag[4][4] = {}, au[4][4] = {};
    const int NPAN = NH / 16;
    for (int p = 0; p < NPAN; p++) {
        int buf = p & 1;
        if (p + 1 < NPAN) {
            aptr += 16; wgp += (size_t)16 * NF; wup += (size_t)16 * NF;
            sa0 = *(const float4*)(aptr);
            sa1 = *(const float4*)(aptr + 4);
            sbg = *(const float4*)(wgp);
            sbu = *(const float4*)(wup);
        }
        {
            const float (*Ab)[128] = As[buf];
            const float (*Gb)[64]  = Bg[buf];
            const float (*Ub)[64]  = Bu[buf];
#pragma unroll
            for (int kk = 0; kk < 16; kk++) {
                ulonglong2 av0 = *(const ulonglong2*)&Ab[kk][m0];
                ulonglong2 av1 = *(const ulonglong2*)&Ab[kk][m0 + 4];
                float2 g0 = *(const float2*)&Gb[kk][ln2];
                float2 g1 = *(const float2*)&Gb[kk][ln2 + 32];
                float2 u0 = *(const float2*)&Ub[kk][ln2];
                float2 u1 = *(const float2*)&Ub[kk][ln2 + 32];
                ull ap[4] = {av0.x, av0.y, av1.x, av1.y};
                ull dg[4] = {dup2(g0.x), dup2(g0.y), dup2(g1.x), dup2(g1.y)};
                ull du[4] = {dup2(u0.x), dup2(u0.y), dup2(u1.x), dup2(u1.y)};
#pragma unroll
                for (int mp = 0; mp < 4; mp++)
#pragma unroll
                    for (int n = 0; n < 4; n++) {
                        ffma2(ag[mp][n], ap[mp], dg[n]);
                        ffma2(au[mp][n], ap[mp], du[n]);
                    }
            }
        }
        if (p + 1 < NPAN) {
            int nb = buf ^ 1;
#pragma unroll
            for (int j = 0; j < 4; j++) As[nb][akq * 8 + j][am] = ((const float*)&sa0)[j];
#pragma unroll
            for (int j = 0; j < 4; j++) As[nb][akq * 8 + 4 + j][am] = ((const float*)&sa1)[j];
            *(float4*)&Bg[nb][bk][bn] = sbg;
            *(float4*)&Bu[nb][bk][bn] = sbu;
        }
        __syncthreads();
    }

    float* hbase = g_hbuf + (size_t)e * NCAP * NF + nblk;
#pragma unroll
    for (int mp = 0; mp < 4; mp++) {
        float2 gv[4], uv[4];
#pragma unroll
        for (int n = 0; n < 4; n++) { gv[n] = unpk(ag[mp][n]); uv[n] = unpk(au[mp][n]); }
#pragma unroll
        for (int h = 0; h < 2; h++) {
            int r = m0 + mp * 2 + h;
            if (row0 + r >= cnt) continue;
            float x0 = silu(h ? gv[0].y : gv[0].x) * (h ? uv[0].y : uv[0].x);
            float x1 = silu(h ? gv[1].y : gv[1].x) * (h ? uv[1].y : uv[1].x);
            float x2 = silu(h ? gv[2].y : gv[2].x) * (h ? uv[2].y : uv[2].x);
            float x3 = silu(h ? gv[3].y : gv[3].x) * (h ? uv[3].y : uv[3].x);
            float* hp = hbase + (size_t)(row0 + r) * NF;
            *(float2*)(hp + ln2)      = make_float2(x0, x1);
            *(float2*)(hp + ln2 + 32) = make_float2(x2, x3);
        }
    }
}

// ---------------- shared SwiGLU GEMM1: sbuf = silu(X@Wg)*(X@Wu) -------------
__global__ __launch_bounds__(256) void shared_gemm1(const float* __restrict__ X,
                                                    const float* __restrict__ Wg,
                                                    const float* __restrict__ Wu) {
    int row0 = blockIdx.y * 128;
    int nblk = blockIdx.x * 64;

    __shared__ __align__(16) float As[2][16][128];
    __shared__ __align__(16) float Bg[2][16][64];
    __shared__ __align__(16) float Bu[2][16][64];

    int tid = threadIdx.x;
    int am = tid >> 1, akq = tid & 1;
    int bk = tid >> 4, bn = (tid & 15) * 4;
    const float* aptr = X + (size_t)(row0 + am) * NH + akq * 8;
    const float* wgp = Wg + (size_t)bk * NF + nblk + bn;
    const float* wup = Wu + (size_t)bk * NF + nblk + bn;

    int w = tid >> 5, lane = tid & 31;
    int m0 = w * 16 + (lane & 1) * 8;
    int ln2 = (lane >> 1) * 2;

    float4 sa0, sa1, sbg, sbu;
    sa0 = *(const float4*)(aptr);
    sa1 = *(const float4*)(aptr + 4);
    sbg = *(const float4*)(wgp);
    sbu = *(const float4*)(wup);
#pragma unroll
    for (int j = 0; j < 4; j++) As[0][akq * 8 + j][am] = ((const float*)&sa0)[j];
#pragma unroll
    for (int j = 0; j < 4; j++) As[0][akq * 8 + 4 + j][am] = ((const float*)&sa1)[j];
    *(float4*)&Bg[0][bk][bn] = sbg;
    *(float4*)&Bu[0][bk][bn] = sbu;
    __syncthreads();

    ull ag[4][4] = {}, au[4][4] = {};
    const int NPAN = NH / 16;
    for (int p = 0; p < NPAN; p++) {
        int buf = p & 1;
        if (p + 1 < NPAN) {
            aptr += 16; wgp += (size_t)16 * NF; wup += (size_t)16 * NF;
            sa0 = *(const float4*)(aptr);
            sa1 = *(const float4*)(aptr + 4);
            sbg = *(const float4*)(wgp);
            sbu = *(const float4*)(wup);
        }
        {
            const float (*Ab)[128] = As[buf];
            const float (*Gb)[64]  = Bg[buf];
            const float (*Ub)[64]  = Bu[buf];
#pragma unroll
            for (int kk = 0; kk < 16; kk++) {
                ulonglong2 av0 = *(const ulonglong2*)&Ab[kk][m0];
                ulonglong2 av1 = *(const ulonglong2*)&Ab[kk][m0 + 4];
                float2 g0 = *(const float2*)&Gb[kk][ln2];
                float2 g1 = *(const float2*)&Gb[kk][ln2 + 32];
                float2 u0 = *(const float2*)&Ub[kk][ln2];
                float2 u1 = *(const float2*)&Ub[kk][ln2 + 32];
                ull ap[4] = {av0.x, av0.y, av1.x, av1.y};
                ull dg[4] = {dup2(g0.x), dup2(g0.y), dup2(g1.x), dup2(g1.y)};
                ull du[4] = {dup2(u0.x), dup2(u0.y), dup2(u1.x), dup2(u1.y)};
#pragma unroll
                for (int mp = 0; mp < 4; mp++)
#pragma unroll
                    for (int n = 0; n < 4; n++) {
                        ffma2(ag[mp][n], ap[mp], dg[n]);
                        ffma2(au[mp][n], ap[mp], du[n]);
                    }
            }
        }
        if (p + 1 < NPAN) {
            int nb = buf ^ 1;
#pragma unroll
            for (int j = 0; j < 4; j++) As[nb][akq * 8 + j][am] = ((const float*)&sa0)[j];
#pragma unroll
            for (int j = 0; j < 4; j++) As[nb][akq * 8 + 4 + j][am] = ((const float*)&sa1)[j];
            *(float4*)&Bg[nb][bk][bn] = sbg;
            *(float4*)&Bu[nb][bk][bn] = sbu;
        }
        __syncthreads();
    }

#pragma unroll
    for (int mp = 0; mp < 4; mp++) {
        float2 gv[4], uv[4];
#pragma unroll
        for (int n = 0; n < 4; n++) { gv[n] = unpk(ag[mp][n]); uv[n] = unpk(au[mp][n]); }
#pragma unroll
        for (int h = 0; h < 2; h++) {
            int r = row0 + m0 + mp * 2 + h;
            float x0 = silu(h ? gv[0].y : gv[0].x) * (h ? uv[0].y : uv[0].x);
            float x1 = silu(h ? gv[1].y : gv[1].x) * (h ? uv[1].y : uv[1].x);
            float x2 = silu(h ? gv[2].y : gv[2].x) * (h ? uv[2].y : uv[2].x);
            float x3 = silu(h ? gv[3].y : gv[3].x) * (h ? uv[3].y : uv[3].x);
            float* hp = g_sbuf + (size_t)r * NF + nblk;
            *(float2*)(hp + ln2)      = make_float2(x0, x1);
            *(float2*)(hp + ln2 + 32) = make_float2(x2, x3);
        }
    }
}

// ============================================================================
// GEMM2-type: C = A[128,K] @ B[K,128]. CTA 128x128, K-panel 16, f32x2.
// Per thread: 8(M) x 8(N), pairs along M.
// ============================================================================

// ---------------- routed down GEMM: out += w * (hbuf @ Wd) ------------------
__global__ __launch_bounds__(256) void moe_gemm2(const float* __restrict__ Wd,
                                                 float* __restrict__ out) {
    int e = blockIdx.z;
    int cnt = g_cnt[e]; if (cnt > NCAP) cnt = NCAP;
    int row0 = blockIdx.y * 128;
    if (row0 >= cnt) return;
    int nblk = blockIdx.x * 128;

    __shared__ __align__(16) float As[2][16][128];
    __shared__ __align__(16) float Bs[2][16][128];
    __shared__ int   stok[128];
    __shared__ float swgt[128];

    int tid = threadIdx.x;
    if (tid < 128) {
        int r = row0 + tid;
        stok[tid] = (r < cnt) ? g_tok[e * NCAP + r] : -1;
        swgt[tid] = (r < cnt) ? g_wgt[e * NCAP + r] : 0.f;
    }
    __syncthreads();

    const float* hb = g_hbuf + (size_t)e * NCAP * NF;
    const float* wd = Wd + (size_t)e * NF * NH;

    int am = tid >> 1, akq = tid & 1;
    int bk = tid >> 4, bn = (tid & 15) * 4;
    const float* aptr = hb + (size_t)(row0 + am) * NF + akq * 8;
    const float* bptr = wd + (size_t)bk * NH + nblk + bn;

    int w = tid >> 5, lane = tid & 31;
    int m0 = (w & 3) * 32 + (lane >> 3) * 8;
    int na = (w >> 2) * 64 + (lane & 7) * 4;   // cols na..na+3 and na+32..na+35

    float4 sa0, sa1, sb0, sb1;
    sa0 = *(const float4*)(aptr);
    sa1 = *(const float4*)(aptr + 4);
    sb0 = *(const float4*)(bptr);
    sb1 = *(const float4*)(bptr + 64);
#pragma unroll
    for (int j = 0; j < 4; j++) As[0][akq * 8 + j][am] = ((const float*)&sa0)[j];
#pragma unroll
    for (int j = 0; j < 4; j++) As[0][akq * 8 + 4 + j][am] = ((const float*)&sa1)[j];
    *(float4*)&Bs[0][bk][bn] = sb0;
    *(float4*)&Bs[0][bk][bn + 64] = sb1;
    __syncthreads();

    ull acc[4][8] = {};
    const int NPAN = NF / 16;
    for (int p = 0; p < NPAN; p++) {
        int buf = p & 1;
        if (p + 1 < NPAN) {
            aptr += 16; bptr += (size_t)16 * NH;
            sa0 = *(const float4*)(aptr);
            sa1 = *(const float4*)(aptr + 4);
            sb0 = *(const float4*)(bptr);
            sb1 = *(const float4*)(bptr + 64);
        }
        {
            const float (*Ab)[128] = As[buf];
            const float (*Bb)[128] = Bs[buf];
#pragma unroll
            for (int kk = 0; kk < 16; kk++) {
                ulonglong2 av0 = *(const ulonglong2*)&Ab[kk][m0];
                ulonglong2 av1 = *(const ulonglong2*)&Ab[kk][m0 + 4];
                float4 bv0 = *(const float4*)&Bb[kk][na];
                float4 bv1 = *(const float4*)&Bb[kk][na + 32];
                ull ap[4] = {av0.x, av0.y, av1.x, av1.y};
                ull bd[8] = {dup2(bv0.x), dup2(bv0.y), dup2(bv0.z), dup2(bv0.w),
                             dup2(bv1.x), dup2(bv1.y), dup2(bv1.z), dup2(bv1.w)};
#pragma unroll
                for (int mp = 0; mp < 4; mp++)
#pragma unroll
                    for (int n = 0; n < 8; n++)
                        ffma2(acc[mp][n], ap[mp], bd[n]);
            }
        }
        if (p + 1 < NPAN) {
            int nb = buf ^ 1;
#pragma unroll
            for (int j = 0; j < 4; j++) As[nb][akq * 8 + j][am] = ((const float*)&sa0)[j];
#pragma unroll
            for (int j = 0; j < 4; j++) As[nb][akq * 8 + 4 + j][am] = ((const float*)&sa1)[j];
            *(float4*)&Bs[nb][bk][bn] = sb0;
            *(float4*)&Bs[nb][bk][bn + 64] = sb1;
        }
        __syncthreads();
    }

#pragma unroll
    for (int mp = 0; mp < 4; mp++) {
        float2 v[8];
#pragma unroll
        for (int n = 0; n < 8; n++) v[n] = unpk(acc[mp][n]);
#pragma unroll
        for (int h = 0; h < 2; h++) {
            int r = m0 + mp * 2 + h;
            int tok = stok[r];
            if (tok < 0) continue;
            float wt = swgt[r];
            float* op = out + (size_t)tok * NH + nblk;
#pragma unroll
            for (int j = 0; j < 4; j++) {
                float x0 = h ? v[j].y : v[j].x;
                float x1 = h ? v[4 + j].y : v[4 + j].x;
                atomicAdd(op + na + j, x0 * wt);
                atomicAdd(op + na + 32 + j, x1 * wt);
            }
        }
    }
}

// ---------------- shared expert GEMM2: out = sbuf @ Wd (plain store) --------
__global__ __launch_bounds__(256) void shared_gemm2(const float* __restrict__ Wd,
                                                    float* __restrict__ out) {
    int row0 = blockIdx.y * 128;
    int nblk = blockIdx.x * 128;

    __shared__ __align__(16) float As[2][16][128];
    __shared__ __align__(16) float Bs[2][16][128];

    int tid = threadIdx.x;
    int am = tid >> 1, akq = tid & 1;
    int bk = tid >> 4, bn = (tid & 15) * 4;
    const float* aptr = g_sbuf + (size_t)(row0 + am) * NF + akq * 8;
    const float* bptr = Wd + (size_t)bk * NH + nblk + bn;

    int w = tid >> 5, lane = tid & 31;
    int m0 = (w & 3) * 32 + (lane >> 3) * 8;
    int na = (w >> 2) * 64 + (lane & 7) * 4;

    float4 sa0, sa1, sb0, sb1;
    sa0 = *(const float4*)(aptr);
    sa1 = *(const float4*)(aptr + 4);
    sb0 = *(const float4*)(bptr);
    sb1 = *(const float4*)(bptr + 64);
#pragma unroll
    for (int j = 0; j < 4; j++) As[0][akq * 8 + j][am] = ((const float*)&sa0)[j];
#pragma unroll
    for (int j = 0; j < 4; j++) As[0][akq * 8 + 4 + j][am] = ((const float*)&sa1)[j];
    *(float4*)&Bs[0][bk][bn] = sb0;
    *(float4*)&Bs[0][bk][bn + 64] = sb1;
    __syncthreads();

    ull acc[4][8] = {};
    const int NPAN = NF / 16;
    for (int p = 0; p < NPAN; p++) {
        int buf = p & 1;
        if (p + 1 < NPAN) {
            aptr += 16; bptr += (size_t)16 * NH;
            sa0 = *(const float4*)(aptr);
            sa1 = *(const float4*)(aptr + 4);
            sb0 = *(const float4*)(bptr);
            sb1 = *(const float4*)(bptr + 64);
        }
        {
            const float (*Ab)[128] = As[buf];
            const float (*Bb)[128] = Bs[buf];
#pragma unroll
            for (int kk = 0; kk < 16; kk++) {
                ulonglong2 av0 = *(const ulonglong2*)&Ab[kk][m0];
                ulonglong2 av1 = *(const ulonglong2*)&Ab[kk][m0 + 4];
                float4 bv0 = *(const float4*)&Bb[kk][na];
                float4 bv1 = *(const float4*)&Bb[kk][na + 32];
                ull ap[4] = {av0.x, av0.y, av1.x, av1.y};
                ull bd[8] = {dup2(bv0.x), dup2(bv0.y), dup2(bv0.z), dup2(bv0.w),
                             dup2(bv1.x), dup2(bv1.y), dup2(bv1.z), dup2(bv1.w)};
#pragma unroll
                for (int mp = 0; mp < 4; mp++)
#pragma unroll
                    for (int n = 0; n < 8; n++)
                        ffma2(acc[mp][n], ap[mp], bd[n]);
            }
        }
        if (p + 1 < NPAN) {
            int nb = buf ^ 1;
#pragma unroll
            for (int j = 0; j < 4; j++) As[nb][akq * 8 + j][am] = ((const float*)&sa0)[j];
#pragma unroll
            for (int j = 0; j < 4; j++) As[nb][akq * 8 + 4 + j][am] = ((const float*)&sa1)[j];
            *(float4*)&Bs[nb][bk][bn] = sb0;
            *(float4*)&Bs[nb][bk][bn + 64] = sb1;
        }
        __syncthreads();
    }

#pragma unroll
    for (int mp = 0; mp < 4; mp++) {
        float2 v[8];
#pragma unroll
        for (int n = 0; n < 8; n++) v[n] = unpk(acc[mp][n]);
#pragma unroll
        for (int h = 0; h < 2; h++) {
            int r = row0 + m0 + mp * 2 + h;
            float* op = out + (size_t)r * NH + nblk;
            float4 o0, o1;
            o0.x = h ? v[0].y : v[0].x;  o0.y = h ? v[1].y : v[1].x;
            o0.z = h ? v[2].y : v[2].x;  o0.w = h ? v[3].y : v[3].x;
            o1.x = h ? v[4].y : v[4].x;  o1.y = h ? v[5].y : v[5].x;
            o1.z = h ? v[6].y : v[6].x;  o1.w = h ? v[7].y : v[7].x;
            *(float4*)(op + na)      = o0;
            *(float4*)(op + na + 32) = o1;
        }
    }
}

// ---------------------------------------------------------------------------
extern "C" void kernel_launch(void* const* d_in, const int* in_sizes, int n_in,
                              void* d_out, int out_size) {
    const float* x       = (const float*)d_in[0];
    const float* gate_w  = (const float*)d_in[1];
    const float* bias    = (const float*)d_in[2];
    const float* w_gate  = (const float*)d_in[3];
    const float* w_up    = (const float*)d_in[4];
    const float* w_down  = (const float*)d_in[5];
    const float* ws_gate = (const float*)d_in[6];
    const float* ws_up   = (const float*)d_in[7];
    const float* ws_down = (const float*)d_in[8];
    float* out = (float*)d_out;

    zero_cnt_kernel<<<1, 64>>>();
    router_gemm<<<NT / 64, 256>>>(x, gate_w);
    topk_route<<<NT / 256, 256>>>(bias);

    // shared expert first: plain stores initialize the (poisoned) output
    shared_gemm1<<<dim3(NF / 64, NT / 128), 256>>>(x, ws_gate, ws_up);
    shared_gemm2<<<dim3(NH / 128, NT / 128), 256>>>(ws_down, out);

    // routed experts: grouped GEMMs, weighted atomic accumulation into out
    moe_gemm1<<<dim3(NF / 64, NCAP / 128, NE), 256>>>(x, w_gate, w_up);
    moe_gemm2<<<dim3(NH / 128, NCAP / 128, NE), 256>>>(w_down, out);
}

// round 16
// speedup vs baseline: 2.3951x; 2.1265x over previous
#include <cuda_runtime.h>
#include <math.h>

#define NT   2048      // tokens (2*1024)
#define NH   2048      // hidden
#define NE   64        // experts
#define NK   6         // top_k
#define NF   768       // moe intermediate
#define NG   8         // groups
#define EPG  8         // experts per group
#define NKG  4         // topk groups
#define NCAP 384       // capacity per expert
#define RSCALE 2.5f

// ---------------- scratch (device globals; no allocation allowed) ----------
__device__ float g_logits[NT * NE];
__device__ int   g_cnt[NE];
__device__ int   g_tok[NE * NCAP];
__device__ float g_wgt[NE * NCAP];
__device__ float g_hbuf[(size_t)NE * NCAP * NF];   // 75.5 MB
__device__ float g_sbuf[(size_t)NT * NF];          // 6.3 MB

// ---------------- helpers ---------------------------------------------------
__device__ __forceinline__ float silu(float g) {
    return g / (1.f + expf(-g));
}
// fp32 -> tf32 with round-to-nearest (unbiased; truncation would bias -1e-3)
__device__ __forceinline__ unsigned tf32r(float x) {
    unsigned u;
    asm("cvt.rna.tf32.f32 %0, %1;" : "=r"(u) : "f"(x));
    return u;
}
// D += A(16x8) * B(8x8), tf32 inputs, f32 accum
__device__ __forceinline__ void mma8(float c[4], const unsigned a[4],
                                     unsigned b0, unsigned b1) {
    asm volatile(
        "mma.sync.aligned.m16n8k8.row.col.f32.tf32.tf32.f32 "
        "{%0,%1,%2,%3}, {%4,%5,%6,%7}, {%8,%9}, {%0,%1,%2,%3};"
        : "+f"(c[0]), "+f"(c[1]), "+f"(c[2]), "+f"(c[3])
        : "r"(a[0]), "r"(a[1]), "r"(a[2]), "r"(a[3]), "r"(b0), "r"(b1));
}

// ---------------------------------------------------------------------------
__global__ void zero_cnt_kernel() {
    int i = threadIdx.x;
    if (i < NE) g_cnt[i] = 0;
}

// ---------------- router logits (exact fp32 — routing must not flip) --------
__global__ void router_gemm(const float* __restrict__ X,
                            const float* __restrict__ Wg) {
    __shared__ __align__(16) float As[64][16];
    __shared__ __align__(16) float Bs[16][64];
    int bm = blockIdx.x * 64;
    int tid = threadIdx.x;
    int tx = tid & 15, ty = tid >> 4;
    int arow = tid >> 2, akg = tid & 3;
    int brow = tid >> 4, bng = tid & 15;
    float acc[4][4] = {};
    for (int k0 = 0; k0 < NH; k0 += 16) {
        *(float4*)&As[arow][akg * 4] =
            *(const float4*)&X[(size_t)(bm + arow) * NH + k0 + akg * 4];
        *(float4*)&Bs[brow][bng * 4] =
            *(const float4*)&Wg[(size_t)(k0 + brow) * NE + bng * 4];
        __syncthreads();
#pragma unroll
        for (int kk = 0; kk < 16; kk++) {
            float4 b4 = *(const float4*)&Bs[kk][tx * 4];
            float a[4];
#pragma unroll
            for (int i = 0; i < 4; i++) a[i] = As[ty * 4 + i][kk];
#pragma unroll
            for (int i = 0; i < 4; i++) {
                acc[i][0] += a[i] * b4.x;
                acc[i][1] += a[i] * b4.y;
                acc[i][2] += a[i] * b4.z;
                acc[i][3] += a[i] * b4.w;
            }
        }
        __syncthreads();
    }
#pragma unroll
    for (int i = 0; i < 4; i++)
#pragma unroll
        for (int j = 0; j < 4; j++)
            g_logits[(size_t)(bm + ty * 4 + i) * NE + tx * 4 + j] = acc[i][j];
}

// ---------------- grouped top-k routing + scatter ---------------------------
__global__ void topk_route(const float* __restrict__ bias) {
    int t = blockIdx.x * blockDim.x + threadIdx.x;
    if (t >= NT) return;
    float s[NE], sb[NE];
#pragma unroll 8
    for (int e = 0; e < NE; e++) {
        float l = g_logits[(size_t)t * NE + e];
        float sv = 1.f / (1.f + expf(-l));
        s[e] = sv;
        sb[e] = sv + bias[e];
    }
    float gsc[NG];
#pragma unroll
    for (int g = 0; g < NG; g++) {
        float m1 = -INFINITY, m2 = -INFINITY;
#pragma unroll
        for (int j = 0; j < EPG; j++) {
            float v = sb[g * EPG + j];
            if (v > m1) { m2 = m1; m1 = v; }
            else if (v > m2) { m2 = v; }
        }
        gsc[g] = m1 + m2;
    }
    bool gsel[NG];
#pragma unroll
    for (int g = 0; g < NG; g++) gsel[g] = false;
    for (int r = 0; r < NKG; r++) {
        int bi = 0; float bv = -INFINITY;
        for (int g = 0; g < NG; g++)
            if (!gsel[g] && gsc[g] > bv) { bv = gsc[g]; bi = g; }
        gsel[bi] = true;
    }
    bool used[NE];
#pragma unroll
    for (int e = 0; e < NE; e++) used[e] = false;
    int ids[NK];
    float ws[NK];
    float wsum = 0.f;
    for (int r = 0; r < NK; r++) {
        int bi = 0; float bv = -INFINITY;
        for (int e = 0; e < NE; e++) {
            if (used[e] || !gsel[e / EPG]) continue;
            if (sb[e] > bv) { bv = sb[e]; bi = e; }
        }
        used[bi] = true;
        ids[r] = bi;
        ws[r] = s[bi];
        wsum += s[bi];
    }
    float inv = RSCALE / wsum;
    for (int r = 0; r < NK; r++) {
        int e = ids[r];
        int slot = atomicAdd(&g_cnt[e], 1);
        if (slot < NCAP) {
            g_tok[e * NCAP + slot] = t;
            g_wgt[e * NCAP + slot] = ws[r] * inv;
        }
    }
}

// ============================================================================
// TF32 tensor-core GEMMs (mma.sync.m16n8k8). CTA 128 x {64|128}, K-panel 16,
// double-buffered SMEM. SMEM row stride chosen ≡ 8 (mod 32) words so that
// fragment LDS.32 (k in lane%4{,+4}, m/n in lane>>2) is bank-conflict-free.
// Warp layout: 8 warps = 4(M) x 2(N); warp tile 32 x {32|64}.
// Fragment maps (per PTX m16n8k8):
//   A: a0=(r=lq, k=lr) a1=(lq+8,lr) a2=(lq,lr+4) a3=(lq+8,lr+4)
//   B: b0=(k=lr, n=lq) b1=(lr+4, lq)
//   C: c0=(lq, 2lr) c1=(lq, 2lr+1) c2=(lq+8, 2lr) c3=(lq+8, 2lr+1)
// ============================================================================

// ---------------- routed SwiGLU GEMM1: hbuf = silu(Xe@Wg) * (Xe@Wu) ---------
__global__ __launch_bounds__(256, 2) void moe_gemm1(const float* __restrict__ X,
                                                    const float* __restrict__ Wg,
                                                    const float* __restrict__ Wu) {
    int e = blockIdx.z;
    int cnt = g_cnt[e]; if (cnt > NCAP) cnt = NCAP;
    int row0 = blockIdx.y * 128;
    if (row0 >= cnt) return;
    int nblk = blockIdx.x * 64;

    __shared__ unsigned As[2][16][136];   // [k][row], stride 136 (8 mod 32)
    __shared__ unsigned Bg[2][16][72];    // [k][n],   stride 72  (8 mod 32)
    __shared__ unsigned Bu[2][16][72];
    __shared__ int stok[128];

    int tid = threadIdx.x;
    if (tid < 128) {
        int r = row0 + tid;
        stok[tid] = (r < cnt) ? g_tok[e * NCAP + r] : 0;
    }
    __syncthreads();

    int ar = tid >> 1, ah = tid & 1;                  // A: row ar, k-half ah
    int bk = tid >> 4, bn = (tid & 15) * 4;           // B: row bk, 4 cols
    const float* aptr = X + (size_t)stok[ar] * NH + ah * 8;
    const float* wgp = Wg + (size_t)e * NH * NF + (size_t)bk * NF + nblk + bn;
    const float* wup = Wu + (size_t)e * NH * NF + (size_t)bk * NF + nblk + bn;

    int lane = tid & 31, w = tid >> 5;
    int m0 = (w & 3) * 32, n0 = (w >> 2) * 32;
    int lq = lane >> 2, lr = lane & 3;

    float4 av0, av1, gv, uv;
    av0 = *(const float4*)(aptr);
    av1 = *(const float4*)(aptr + 4);
    gv  = *(const float4*)(wgp);
    uv  = *(const float4*)(wup);
    {
#pragma unroll
        for (int j = 0; j < 4; j++) {
            As[0][ah * 8 + j][ar]     = tf32r(((const float*)&av0)[j]);
            As[0][ah * 8 + 4 + j][ar] = tf32r(((const float*)&av1)[j]);
        }
        uint4 tg, tu;
        tg.x = tf32r(gv.x); tg.y = tf32r(gv.y); tg.z = tf32r(gv.z); tg.w = tf32r(gv.w);
        tu.x = tf32r(uv.x); tu.y = tf32r(uv.y); tu.z = tf32r(uv.z); tu.w = tf32r(uv.w);
        *(uint4*)&Bg[0][bk][bn] = tg;
        *(uint4*)&Bu[0][bk][bn] = tu;
    }
    __syncthreads();

    float ag[2][4][4] = {}, au[2][4][4] = {};
    const int NPAN = NH / 16;
    for (int p = 0; p < NPAN; p++) {
        int buf = p & 1;
        if (p + 1 < NPAN) {
            aptr += 16; wgp += (size_t)16 * NF; wup += (size_t)16 * NF;
            av0 = *(const float4*)(aptr);
            av1 = *(const float4*)(aptr + 4);
            gv  = *(const float4*)(wgp);
            uv  = *(const float4*)(wup);
        }
#pragma unroll
        for (int kk = 0; kk < 2; kk++) {
            int kb = kk * 8;
            unsigned a[2][4];
#pragma unroll
            for (int i = 0; i < 2; i++) {
                int rb = m0 + i * 16 + lq;
                a[i][0] = As[buf][kb + lr][rb];
                a[i][1] = As[buf][kb + lr][rb + 8];
                a[i][2] = As[buf][kb + lr + 4][rb];
                a[i][3] = As[buf][kb + lr + 4][rb + 8];
            }
#pragma unroll
            for (int j = 0; j < 4; j++) {
                int nn = n0 + j * 8 + lq;
                unsigned g0 = Bg[buf][kb + lr][nn];
                unsigned g1 = Bg[buf][kb + lr + 4][nn];
                unsigned u0 = Bu[buf][kb + lr][nn];
                unsigned u1 = Bu[buf][kb + lr + 4][nn];
#pragma unroll
                for (int i = 0; i < 2; i++) {
                    mma8(ag[i][j], a[i], g0, g1);
                    mma8(au[i][j], a[i], u0, u1);
                }
            }
        }
        if (p + 1 < NPAN) {
            int nb = buf ^ 1;
#pragma unroll
            for (int j = 0; j < 4; j++) {
                As[nb][ah * 8 + j][ar]     = tf32r(((const float*)&av0)[j]);
                As[nb][ah * 8 + 4 + j][ar] = tf32r(((const float*)&av1)[j]);
            }
            uint4 tg, tu;
            tg.x = tf32r(gv.x); tg.y = tf32r(gv.y); tg.z = tf32r(gv.z); tg.w = tf32r(gv.w);
            tu.x = tf32r(uv.x); tu.y = tf32r(uv.y); tu.z = tf32r(uv.z); tu.w = tf32r(uv.w);
            *(uint4*)&Bg[nb][bk][bn] = tg;
            *(uint4*)&Bu[nb][bk][bn] = tu;
        }
        __syncthreads();
    }

    float* hbase = g_hbuf + (size_t)e * NCAP * NF + nblk;
#pragma unroll
    for (int i = 0; i < 2; i++)
#pragma unroll
        for (int h = 0; h < 2; h++) {
            int rl = m0 + i * 16 + lq + h * 8;
            if (row0 + rl >= cnt) continue;
            float* hp = hbase + (size_t)(row0 + rl) * NF;
#pragma unroll
            for (int j = 0; j < 4; j++) {
                float x0 = silu(ag[i][j][h * 2])     * au[i][j][h * 2];
                float x1 = silu(ag[i][j][h * 2 + 1]) * au[i][j][h * 2 + 1];
                *(float2*)(hp + n0 + j * 8 + 2 * lr) = make_float2(x0, x1);
            }
        }
}

// ---------------- shared SwiGLU GEMM1: sbuf = silu(X@Wg)*(X@Wu) -------------
__global__ __launch_bounds__(256, 2) void shared_gemm1(const float* __restrict__ X,
                                                       const float* __restrict__ Wg,
                                                       const float* __restrict__ Wu) {
    int row0 = blockIdx.y * 128;
    int nblk = blockIdx.x * 64;

    __shared__ unsigned As[2][16][136];
    __shared__ unsigned Bg[2][16][72];
    __shared__ unsigned Bu[2][16][72];

    int tid = threadIdx.x;
    int ar = tid >> 1, ah = tid & 1;
    int bk = tid >> 4, bn = (tid & 15) * 4;
    const float* aptr = X + (size_t)(row0 + ar) * NH + ah * 8;
    const float* wgp = Wg + (size_t)bk * NF + nblk + bn;
    const float* wup = Wu + (size_t)bk * NF + nblk + bn;

    int lane = tid & 31, w = tid >> 5;
    int m0 = (w & 3) * 32, n0 = (w >> 2) * 32;
    int lq = lane >> 2, lr = lane & 3;

    float4 av0, av1, gv, uv;
    av0 = *(const float4*)(aptr);
    av1 = *(const float4*)(aptr + 4);
    gv  = *(const float4*)(wgp);
    uv  = *(const float4*)(wup);
    {
#pragma unroll
        for (int j = 0; j < 4; j++) {
            As[0][ah * 8 + j][ar]     = tf32r(((const float*)&av0)[j]);
            As[0][ah * 8 + 4 + j][ar] = tf32r(((const float*)&av1)[j]);
        }
        uint4 tg, tu;
        tg.x = tf32r(gv.x); tg.y = tf32r(gv.y); tg.z = tf32r(gv.z); tg.w = tf32r(gv.w);
        tu.x = tf32r(uv.x); tu.y = tf32r(uv.y); tu.z = tf32r(uv.z); tu.w = tf32r(uv.w);
        *(uint4*)&Bg[0][bk][bn] = tg;
        *(uint4*)&Bu[0][bk][bn] = tu;
    }
    __syncthreads();

    float ag[2][4][4] = {}, au[2][4][4] = {};
    const int NPAN = NH / 16;
    for (int p = 0; p < NPAN; p++) {
        int buf = p & 1;
        if (p + 1 < NPAN) {
            aptr += 16; wgp += (size_t)16 * NF; wup += (size_t)16 * NF;
            av0 = *(const float4*)(aptr);
            av1 = *(const float4*)(aptr + 4);
            gv  = *(const float4*)(wgp);
            uv  = *(const float4*)(wup);
        }
#pragma unroll
        for (int kk = 0; kk < 2; kk++) {
            int kb = kk * 8;
            unsigned a[2][4];
#pragma unroll
            for (int i = 0; i < 2; i++) {
                int rb = m0 + i * 16 + lq;
                a[i][0] = As[buf][kb + lr][rb];
                a[i][1] = As[buf][kb + lr][rb + 8];
                a[i][2] = As[buf][kb + lr + 4][rb];
                a[i][3] = As[buf][kb + lr + 4][rb + 8];
            }
#pragma unroll
            for (int j = 0; j < 4; j++) {
                int nn = n0 + j * 8 + lq;
                unsigned g0 = Bg[buf][kb + lr][nn];
                unsigned g1 = Bg[buf][kb + lr + 4][nn];
                unsigned u0 = Bu[buf][kb + lr][nn];
                unsigned u1 = Bu[buf][kb + lr + 4][nn];
#pragma unroll
                for (int i = 0; i < 2; i++) {
                    mma8(ag[i][j], a[i], g0, g1);
                    mma8(au[i][j], a[i], u0, u1);
                }
            }
        }
        if (p + 1 < NPAN) {
            int nb = buf ^ 1;
#pragma unroll
            for (int j = 0; j < 4; j++) {
                As[nb][ah * 8 + j][ar]     = tf32r(((const float*)&av0)[j]);
                As[nb][ah * 8 + 4 + j][ar] = tf32r(((const float*)&av1)[j]);
            }
            uint4 tg, tu;
            tg.x = tf32r(gv.x); tg.y = tf32r(gv.y); tg.z = tf32r(gv.z); tg.w = tf32r(gv.w);
            tu.x = tf32r(uv.x); tu.y = tf32r(uv.y); tu.z = tf32r(uv.z); tu.w = tf32r(uv.w);
            *(uint4*)&Bg[nb][bk][bn] = tg;
            *(uint4*)&Bu[nb][bk][bn] = tu;
        }
        __syncthreads();
    }

#pragma unroll
    for (int i = 0; i < 2; i++)
#pragma unroll
        for (int h = 0; h < 2; h++) {
            int rl = m0 + i * 16 + lq + h * 8;
            float* hp = g_sbuf + (size_t)(row0 + rl) * NF + nblk;
#pragma unroll
            for (int j = 0; j < 4; j++) {
                float x0 = silu(ag[i][j][h * 2])     * au[i][j][h * 2];
                float x1 = silu(ag[i][j][h * 2 + 1]) * au[i][j][h * 2 + 1];
                *(float2*)(hp + n0 + j * 8 + 2 * lr) = make_float2(x0, x1);
            }
        }
}

// ---------------- routed down GEMM: out += w * (hbuf @ Wd) ------------------
__global__ __launch_bounds__(256, 2) void moe_gemm2(const float* __restrict__ Wd,
                                                    float* __restrict__ out) {
    int e = blockIdx.z;
    int cnt = g_cnt[e]; if (cnt > NCAP) cnt = NCAP;
    int row0 = blockIdx.y * 128;
    if (row0 >= cnt) return;
    int nblk = blockIdx.x * 128;

    __shared__ unsigned As[2][16][136];
    __shared__ unsigned Bs[2][16][136];
    __shared__ int   stok[128];
    __shared__ float swgt[128];

    int tid = threadIdx.x;
    if (tid < 128) {
        int r = row0 + tid;
        stok[tid] = (r < cnt) ? g_tok[e * NCAP + r] : -1;
        swgt[tid] = (r < cnt) ? g_wgt[e * NCAP + r] : 0.f;
    }
    __syncthreads();

    const float* hb = g_hbuf + (size_t)e * NCAP * NF;
    const float* wd = Wd + (size_t)e * NF * NH;

    int ar = tid >> 1, ah = tid & 1;
    int bk = tid >> 4, bn = (tid & 15) * 8;
    const float* aptr = hb + (size_t)(row0 + ar) * NF + ah * 8;
    const float* bptr = wd + (size_t)bk * NH + nblk + bn;

    int lane = tid & 31, w = tid >> 5;
    int m0 = (w & 3) * 32, n0 = (w >> 2) * 64;
    int lq = lane >> 2, lr = lane & 3;

    float4 av0, av1, bv0, bv1;
    av0 = *(const float4*)(aptr);
    av1 = *(const float4*)(aptr + 4);
    bv0 = *(const float4*)(bptr);
    bv1 = *(const float4*)(bptr + 4);
    {
#pragma unroll
        for (int j = 0; j < 4; j++) {
            As[0][ah * 8 + j][ar]     = tf32r(((const float*)&av0)[j]);
            As[0][ah * 8 + 4 + j][ar] = tf32r(((const float*)&av1)[j]);
        }
        uint4 t0, t1;
        t0.x = tf32r(bv0.x); t0.y = tf32r(bv0.y); t0.z = tf32r(bv0.z); t0.w = tf32r(bv0.w);
        t1.x = tf32r(bv1.x); t1.y = tf32r(bv1.y); t1.z = tf32r(bv1.z); t1.w = tf32r(bv1.w);
        *(uint4*)&Bs[0][bk][bn]     = t0;
        *(uint4*)&Bs[0][bk][bn + 4] = t1;
    }
    __syncthreads();

    float acc[2][8][4] = {};
    const int NPAN = NF / 16;
    for (int p = 0; p < NPAN; p++) {
        int buf = p & 1;
        if (p + 1 < NPAN) {
            aptr += 16; bptr += (size_t)16 * NH;
            av0 = *(const float4*)(aptr);
            av1 = *(const float4*)(aptr + 4);
            bv0 = *(const float4*)(bptr);
            bv1 = *(const float4*)(bptr + 4);
        }
#pragma unroll
        for (int kk = 0; kk < 2; kk++) {
            int kb = kk * 8;
            unsigned a[2][4];
#pragma unroll
            for (int i = 0; i < 2; i++) {
                int rb = m0 + i * 16 + lq;
                a[i][0] = As[buf][kb + lr][rb];
                a[i][1] = As[buf][kb + lr][rb + 8];
                a[i][2] = As[buf][kb + lr + 4][rb];
                a[i][3] = As[buf][kb + lr + 4][rb + 8];
            }
#pragma unroll
            for (int j = 0; j < 8; j++) {
                int nn = n0 + j * 8 + lq;
                unsigned b0 = Bs[buf][kb + lr][nn];
                unsigned b1 = Bs[buf][kb + lr + 4][nn];
#pragma unroll
                for (int i = 0; i < 2; i++)
                    mma8(acc[i][j], a[i], b0, b1);
            }
        }
        if (p + 1 < NPAN) {
            int nb = buf ^ 1;
#pragma unroll
            for (int j = 0; j < 4; j++) {
                As[nb][ah * 8 + j][ar]     = tf32r(((const float*)&av0)[j]);
                As[nb][ah * 8 + 4 + j][ar] = tf32r(((const float*)&av1)[j]);
            }
            uint4 t0, t1;
            t0.x = tf32r(bv0.x); t0.y = tf32r(bv0.y); t0.z = tf32r(bv0.z); t0.w = tf32r(bv0.w);
            t1.x = tf32r(bv1.x); t1.y = tf32r(bv1.y); t1.z = tf32r(bv1.z); t1.w = tf32r(bv1.w);
            *(uint4*)&Bs[nb][bk][bn]     = t0;
            *(uint4*)&Bs[nb][bk][bn + 4] = t1;
        }
        __syncthreads();
    }

#pragma unroll
    for (int i = 0; i < 2; i++)
#pragma unroll
        for (int h = 0; h < 2; h++) {
            int rl = m0 + i * 16 + lq + h * 8;
            int tok = stok[rl];
            if (tok < 0) continue;
            float wt = swgt[rl];
            float* op = out + (size_t)tok * NH + nblk;
#pragma unroll
            for (int j = 0; j < 8; j++) {
                int col = n0 + j * 8 + 2 * lr;
                atomicAdd(op + col,     acc[i][j][h * 2]     * wt);
                atomicAdd(op + col + 1, acc[i][j][h * 2 + 1] * wt);
            }
        }
}

// ---------------- shared expert GEMM2: out = sbuf @ Wd (plain store) --------
__global__ __launch_bounds__(256, 2) void shared_gemm2(const float* __restrict__ Wd,
                                                       float* __restrict__ out) {
    int row0 = blockIdx.y * 128;
    int nblk = blockIdx.x * 128;

    __shared__ unsigned As[2][16][136];
    __shared__ unsigned Bs[2][16][136];

    int tid = threadIdx.x;
    int ar = tid >> 1, ah = tid & 1;
    int bk = tid >> 4, bn = (tid & 15) * 8;
    const float* aptr = g_sbuf + (size_t)(row0 + ar) * NF + ah * 8;
    const float* bptr = Wd + (size_t)bk * NH + nblk + bn;

    int lane = tid & 31, w = tid >> 5;
    int m0 = (w & 3) * 32, n0 = (w >> 2) * 64;
    int lq = lane >> 2, lr = lane & 3;

    float4 av0, av1, bv0, bv1;
    av0 = *(const float4*)(aptr);
    av1 = *(const float4*)(aptr + 4);
    bv0 = *(const float4*)(bptr);
    bv1 = *(const float4*)(bptr + 4);
    {
#pragma unroll
        for (int j = 0; j < 4; j++) {
            As[0][ah * 8 + j][ar]     = tf32r(((const float*)&av0)[j]);
            As[0][ah * 8 + 4 + j][ar] = tf32r(((const float*)&av1)[j]);
        }
        uint4 t0, t1;
        t0.x = tf32r(bv0.x); t0.y = tf32r(bv0.y); t0.z = tf32r(bv0.z); t0.w = tf32r(bv0.w);
        t1.x = tf32r(bv1.x); t1.y = tf32r(bv1.y); t1.z = tf32r(bv1.z); t1.w = tf32r(bv1.w);
        *(uint4*)&Bs[0][bk][bn]     = t0;
        *(uint4*)&Bs[0][bk][bn + 4] = t1;
    }
    __syncthreads();

    float acc[2][8][4] = {};
    const int NPAN = NF / 16;
    for (int p = 0; p < NPAN; p++) {
        int buf = p & 1;
        if (p + 1 < NPAN) {
            aptr += 16; bptr += (size_t)16 * NH;
            av0 = *(const float4*)(aptr);
            av1 = *(const float4*)(aptr + 4);
            bv0 = *(const float4*)(bptr);
            bv1 = *(const float4*)(bptr + 4);
        }
#pragma unroll
        for (int kk = 0; kk < 2; kk++) {
            int kb = kk * 8;
            unsigned a[2][4];
#pragma unroll
            for (int i = 0; i < 2; i++) {
                int rb = m0 + i * 16 + lq;
                a[i][0] = As[buf][kb + lr][rb];
                a[i][1] = As[buf][kb + lr][rb + 8];
                a[i][2] = As[buf][kb + lr + 4][rb];
                a[i][3] = As[buf][kb + lr + 4][rb + 8];
            }
#pragma unroll
            for (int j = 0; j < 8; j++) {
                int nn = n0 + j * 8 + lq;
                unsigned b0 = Bs[buf][kb + lr][nn];
                unsigned b1 = Bs[buf][kb + lr + 4][nn];
#pragma unroll
                for (int i = 0; i < 2; i++)
                    mma8(acc[i][j], a[i], b0, b1);
            }
        }
        if (p + 1 < NPAN) {
            int nb = buf ^ 1;
#pragma unroll
            for (int j = 0; j < 4; j++) {
                As[nb][ah * 8 + j][ar]     = tf32r(((const float*)&av0)[j]);
                As[nb][ah * 8 + 4 + j][ar] = tf32r(((const float*)&av1)[j]);
            }
            uint4 t0, t1;
            t0.x = tf32r(bv0.x); t0.y = tf32r(bv0.y); t0.z = tf32r(bv0.z); t0.w = tf32r(bv0.w);
            t1.x = tf32r(bv1.x); t1.y = tf32r(bv1.y); t1.z = tf32r(bv1.z); t1.w = tf32r(bv1.w);
            *(uint4*)&Bs[nb][bk][bn]     = t0;
            *(uint4*)&Bs[nb][bk][bn + 4] = t1;
        }
        __syncthreads();
    }

#pragma unroll
    for (int i = 0; i < 2; i++)
#pragma unroll
        for (int h = 0; h < 2; h++) {
            int rl = row0 + m0 + i * 16 + lq + h * 8;
            float* op = out + (size_t)rl * NH + nblk;
#pragma unroll
            for (int j = 0; j < 8; j++) {
                int col = n0 + j * 8 + 2 * lr;
                *(float2*)(op + col) =
                    make_float2(acc[i][j][h * 2], acc[i][j][h * 2 + 1]);
            }
        }
}

// ---------------------------------------------------------------------------
extern "C" void kernel_launch(void* const* d_in, const int* in_sizes, int n_in,
                              void* d_out, int out_size) {
    const float* x       = (const float*)d_in[0];
    const float* gate_w  = (const float*)d_in[1];
    const float* bias    = (const float*)d_in[2];
    const float* w_gate  = (const float*)d_in[3];
    const float* w_up    = (const float*)d_in[4];
    const float* w_down  = (const float*)d_in[5];
    const float* ws_gate = (const float*)d_in[6];
    const float* ws_up   = (const float*)d_in[7];
    const float* ws_down = (const float*)d_in[8];
    float* out = (float*)d_out;

    zero_cnt_kernel<<<1, 64>>>();
    router_gemm<<<NT / 64, 256>>>(x, gate_w);
    topk_route<<<NT / 256, 256>>>(bias);

    // shared expert first: plain stores initialize the (poisoned) output
    shared_gemm1<<<dim3(NF / 64, NT / 128), 256>>>(x, ws_gate, ws_up);
    shared_gemm2<<<dim3(NH / 128, NT / 128), 256>>>(ws_down, out);

    // routed experts: grouped GEMMs, weighted atomic accumulation into out
    moe_gemm1<<<dim3(NF / 64, NCAP / 128, NE), 256>>>(x, w_gate, w_up);
    moe_gemm2<<<dim3(NH / 128, NCAP / 128, NE), 256>>>(w_down, out);
}

// round 17
// speedup vs baseline: 2.3980x; 1.0012x over previous
#include <cuda_runtime.h>
#include <math.h>

#define NT   2048      // tokens (2*1024)
#define NH   2048      // hidden
#define NE   64        // experts
#define NK   6         // top_k
#define NF   768       // moe intermediate
#define NG   8         // groups
#define EPG  8         // experts per group
#define NKG  4         // topk groups
#define NCAP 384       // capacity per expert
#define RSCALE 2.5f

// ---------------- scratch (device globals; no allocation allowed) ----------
__device__ float g_logits[NT * NE];
__device__ int   g_cnt[NE];
__device__ int   g_tok[NE * NCAP];
__device__ float g_wgt[NE * NCAP];
__device__ float g_hbuf[(size_t)NE * NCAP * NF];   // 75.5 MB
__device__ float g_sbuf[(size_t)NT * NF];          // 6.3 MB

// ---------------- helpers ---------------------------------------------------
__device__ __forceinline__ float silu(float g) {
    return g / (1.f + expf(-g));
}
// fp32 -> tf32 with round-to-nearest (unbiased; truncation would bias -1e-3)
__device__ __forceinline__ unsigned tf32r(float x) {
    unsigned u;
    asm("cvt.rna.tf32.f32 %0, %1;" : "=r"(u) : "f"(x));
    return u;
}
// D += A(16x8) * B(8x8), tf32 inputs, f32 accum
__device__ __forceinline__ void mma8(float c[4], const unsigned a[4],
                                     unsigned b0, unsigned b1) {
    asm volatile(
        "mma.sync.aligned.m16n8k8.row.col.f32.tf32.tf32.f32 "
        "{%0,%1,%2,%3}, {%4,%5,%6,%7}, {%8,%9}, {%0,%1,%2,%3};"
        : "+f"(c[0]), "+f"(c[1]), "+f"(c[2]), "+f"(c[3])
        : "r"(a[0]), "r"(a[1]), "r"(a[2]), "r"(a[3]), "r"(b0), "r"(b1));
}

// ---------------------------------------------------------------------------
__global__ void zero_cnt_kernel() {
    int i = threadIdx.x;
    if (i < NE) g_cnt[i] = 0;
}

// ---------------- router logits (exact fp32 — routing must not flip) --------
__global__ void router_gemm(const float* __restrict__ X,
                            const float* __restrict__ Wg) {
    __shared__ __align__(16) float As[64][16];
    __shared__ __align__(16) float Bs[16][64];
    int bm = blockIdx.x * 64;
    int tid = threadIdx.x;
    int tx = tid & 15, ty = tid >> 4;
    int arow = tid >> 2, akg = tid & 3;
    int brow = tid >> 4, bng = tid & 15;
    float acc[4][4] = {};
    for (int k0 = 0; k0 < NH; k0 += 16) {
        *(float4*)&As[arow][akg * 4] =
            *(const float4*)&X[(size_t)(bm + arow) * NH + k0 + akg * 4];
        *(float4*)&Bs[brow][bng * 4] =
            *(const float4*)&Wg[(size_t)(k0 + brow) * NE + bng * 4];
        __syncthreads();
#pragma unroll
        for (int kk = 0; kk < 16; kk++) {
            float4 b4 = *(const float4*)&Bs[kk][tx * 4];
            float a[4];
#pragma unroll
            for (int i = 0; i < 4; i++) a[i] = As[ty * 4 + i][kk];
#pragma unroll
            for (int i = 0; i < 4; i++) {
                acc[i][0] += a[i] * b4.x;
                acc[i][1] += a[i] * b4.y;
                acc[i][2] += a[i] * b4.z;
                acc[i][3] += a[i] * b4.w;
            }
        }
        __syncthreads();
    }
#pragma unroll
    for (int i = 0; i < 4; i++)
#pragma unroll
        for (int j = 0; j < 4; j++)
            g_logits[(size_t)(bm + ty * 4 + i) * NE + tx * 4 + j] = acc[i][j];
}

// ---------------- grouped top-k routing + scatter ---------------------------
__global__ void topk_route(const float* __restrict__ bias) {
    int t = blockIdx.x * blockDim.x + threadIdx.x;
    if (t >= NT) return;
    float s[NE], sb[NE];
#pragma unroll 8
    for (int e = 0; e < NE; e++) {
        float l = g_logits[(size_t)t * NE + e];
        float sv = 1.f / (1.f + expf(-l));
        s[e] = sv;
        sb[e] = sv + bias[e];
    }
    float gsc[NG];
#pragma unroll
    for (int g = 0; g < NG; g++) {
        float m1 = -INFINITY, m2 = -INFINITY;
#pragma unroll
        for (int j = 0; j < EPG; j++) {
            float v = sb[g * EPG + j];
            if (v > m1) { m2 = m1; m1 = v; }
            else if (v > m2) { m2 = v; }
        }
        gsc[g] = m1 + m2;
    }
    bool gsel[NG];
#pragma unroll
    for (int g = 0; g < NG; g++) gsel[g] = false;
    for (int r = 0; r < NKG; r++) {
        int bi = 0; float bv = -INFINITY;
        for (int g = 0; g < NG; g++)
            if (!gsel[g] && gsc[g] > bv) { bv = gsc[g]; bi = g; }
        gsel[bi] = true;
    }
    bool used[NE];
#pragma unroll
    for (int e = 0; e < NE; e++) used[e] = false;
    int ids[NK];
    float ws[NK];
    float wsum = 0.f;
    for (int r = 0; r < NK; r++) {
        int bi = 0; float bv = -INFINITY;
        for (int e = 0; e < NE; e++) {
            if (used[e] || !gsel[e / EPG]) continue;
            if (sb[e] > bv) { bv = sb[e]; bi = e; }
        }
        used[bi] = true;
        ids[r] = bi;
        ws[r] = s[bi];
        wsum += s[bi];
    }
    float inv = RSCALE / wsum;
    for (int r = 0; r < NK; r++) {
        int e = ids[r];
        int slot = atomicAdd(&g_cnt[e], 1);
        if (slot < NCAP) {
            g_tok[e * NCAP + slot] = t;
            g_wgt[e * NCAP + slot] = ws[r] * inv;
        }
    }
}

// ============================================================================
// TF32 tensor-core GEMMs (mma.sync.m16n8k8). CTA 128 x {64|128}, K-panel 16,
// double-buffered SMEM. SMEM row stride chosen ≡ 8 (mod 32) words so that
// fragment LDS.32 (k in lane%4{,+4}, m/n in lane>>2) is bank-conflict-free.
// Warp layout: 8 warps = 4(M) x 2(N); warp tile 32 x {32|64}.
// Fragment maps (per PTX m16n8k8):
//   A: a0=(r=lq, k=lr) a1=(lq+8,lr) a2=(lq,lr+4) a3=(lq+8,lr+4)
//   B: b0=(k=lr, n=lq) b1=(lr+4, lq)
//   C: c0=(lq, 2lr) c1=(lq, 2lr+1) c2=(lq+8, 2lr) c3=(lq+8, 2lr+1)
// ============================================================================

// ---------------- routed SwiGLU GEMM1: hbuf = silu(Xe@Wg) * (Xe@Wu) ---------
__global__ __launch_bounds__(256, 2) void moe_gemm1(const float* __restrict__ X,
                                                    const float* __restrict__ Wg,
                                                    const float* __restrict__ Wu) {
    int e = blockIdx.z;
    int cnt = g_cnt[e]; if (cnt > NCAP) cnt = NCAP;
    int row0 = blockIdx.y * 128;
    if (row0 >= cnt) return;
    int nblk = blockIdx.x * 64;

    __shared__ unsigned As[2][16][136];   // [k][row], stride 136 (8 mod 32)
    __shared__ unsigned Bg[2][16][72];    // [k][n],   stride 72  (8 mod 32)
    __shared__ unsigned Bu[2][16][72];
    __shared__ int stok[128];

    int tid = threadIdx.x;
    if (tid < 128) {
        int r = row0 + tid;
        stok[tid] = (r < cnt) ? g_tok[e * NCAP + r] : 0;
    }
    __syncthreads();

    int ar = tid >> 1, ah = tid & 1;                  // A: row ar, k-half ah
    int bk = tid >> 4, bn = (tid & 15) * 4;           // B: row bk, 4 cols
    const float* aptr = X + (size_t)stok[ar] * NH + ah * 8;
    const float* wgp = Wg + (size_t)e * NH * NF + (size_t)bk * NF + nblk + bn;
    const float* wup = Wu + (size_t)e * NH * NF + (size_t)bk * NF + nblk + bn;

    int lane = tid & 31, w = tid >> 5;
    int m0 = (w & 3) * 32, n0 = (w >> 2) * 32;
    int lq = lane >> 2, lr = lane & 3;

    float4 av0, av1, gv, uv;
    av0 = *(const float4*)(aptr);
    av1 = *(const float4*)(aptr + 4);
    gv  = *(const float4*)(wgp);
    uv  = *(const float4*)(wup);
    {
#pragma unroll
        for (int j = 0; j < 4; j++) {
            As[0][ah * 8 + j][ar]     = tf32r(((const float*)&av0)[j]);
            As[0][ah * 8 + 4 + j][ar] = tf32r(((const float*)&av1)[j]);
        }
        uint4 tg, tu;
        tg.x = tf32r(gv.x); tg.y = tf32r(gv.y); tg.z = tf32r(gv.z); tg.w = tf32r(gv.w);
        tu.x = tf32r(uv.x); tu.y = tf32r(uv.y); tu.z = tf32r(uv.z); tu.w = tf32r(uv.w);
        *(uint4*)&Bg[0][bk][bn] = tg;
        *(uint4*)&Bu[0][bk][bn] = tu;
    }
    __syncthreads();

    float ag[2][4][4] = {}, au[2][4][4] = {};
    const int NPAN = NH / 16;
    for (int p = 0; p < NPAN; p++) {
        int buf = p & 1;
        if (p + 1 < NPAN) {
            aptr += 16; wgp += (size_t)16 * NF; wup += (size_t)16 * NF;
            av0 = *(const float4*)(aptr);
            av1 = *(const float4*)(aptr + 4);
            gv  = *(const float4*)(wgp);
            uv  = *(const float4*)(wup);
        }
#pragma unroll
        for (int kk = 0; kk < 2; kk++) {
            int kb = kk * 8;
            unsigned a[2][4];
#pragma unroll
            for (int i = 0; i < 2; i++) {
                int rb = m0 + i * 16 + lq;
                a[i][0] = As[buf][kb + lr][rb];
                a[i][1] = As[buf][kb + lr][rb + 8];
                a[i][2] = As[buf][kb + lr + 4][rb];
                a[i][3] = As[buf][kb + lr + 4][rb + 8];
            }
#pragma unroll
            for (int j = 0; j < 4; j++) {
                int nn = n0 + j * 8 + lq;
                unsigned g0 = Bg[buf][kb + lr][nn];
                unsigned g1 = Bg[buf][kb + lr + 4][nn];
                unsigned u0 = Bu[buf][kb + lr][nn];
                unsigned u1 = Bu[buf][kb + lr + 4][nn];
#pragma unroll
                for (int i = 0; i < 2; i++) {
                    mma8(ag[i][j], a[i], g0, g1);
                    mma8(au[i][j], a[i], u0, u1);
                }
            }
        }
        if (p + 1 < NPAN) {
            int nb = buf ^ 1;
#pragma unroll
            for (int j = 0; j < 4; j++) {
                As[nb][ah * 8 + j][ar]     = tf32r(((const float*)&av0)[j]);
                As[nb][ah * 8 + 4 + j][ar] = tf32r(((const float*)&av1)[j]);
            }
            uint4 tg, tu;
            tg.x = tf32r(gv.x); tg.y = tf32r(gv.y); tg.z = tf32r(gv.z); tg.w = tf32r(gv.w);
            tu.x = tf32r(uv.x); tu.y = tf32r(uv.y); tu.z = tf32r(uv.z); tu.w = tf32r(uv.w);
            *(uint4*)&Bg[nb][bk][bn] = tg;
            *(uint4*)&Bu[nb][bk][bn] = tu;
        }
        __syncthreads();
    }

    float* hbase = g_hbuf + (size_t)e * NCAP * NF + nblk;
#pragma unroll
    for (int i = 0; i < 2; i++)
#pragma unroll
        for (int h = 0; h < 2; h++) {
            int rl = m0 + i * 16 + lq + h * 8;
            if (row0 + rl >= cnt) continue;
            float* hp = hbase + (size_t)(row0 + rl) * NF;
#pragma unroll
            for (int j = 0; j < 4; j++) {
                float x0 = silu(ag[i][j][h * 2])     * au[i][j][h * 2];
                float x1 = silu(ag[i][j][h * 2 + 1]) * au[i][j][h * 2 + 1];
                *(float2*)(hp + n0 + j * 8 + 2 * lr) = make_float2(x0, x1);
            }
        }
}

// ---------------- shared SwiGLU GEMM1: sbuf = silu(X@Wg)*(X@Wu) -------------
__global__ __launch_bounds__(256, 2) void shared_gemm1(const float* __restrict__ X,
                                                       const float* __restrict__ Wg,
                                                       const float* __restrict__ Wu) {
    int row0 = blockIdx.y * 128;
    int nblk = blockIdx.x * 64;

    __shared__ unsigned As[2][16][136];
    __shared__ unsigned Bg[2][16][72];
    __shared__ unsigned Bu[2][16][72];

    int tid = threadIdx.x;
    int ar = tid >> 1, ah = tid & 1;
    int bk = tid >> 4, bn = (tid & 15) * 4;
    const float* aptr = X + (size_t)(row0 + ar) * NH + ah * 8;
    const float* wgp = Wg + (size_t)bk * NF + nblk + bn;
    const float* wup = Wu + (size_t)bk * NF + nblk + bn;

    int lane = tid & 31, w = tid >> 5;
    int m0 = (w & 3) * 32, n0 = (w >> 2) * 32;
    int lq = lane >> 2, lr = lane & 3;

    float4 av0, av1, gv, uv;
    av0 = *(const float4*)(aptr);
    av1 = *(const float4*)(aptr + 4);
    gv  = *(const float4*)(wgp);
    uv  = *(const float4*)(wup);
    {
#pragma unroll
        for (int j = 0; j < 4; j++) {
            As[0][ah * 8 + j][ar]     = tf32r(((const float*)&av0)[j]);
            As[0][ah * 8 + 4 + j][ar] = tf32r(((const float*)&av1)[j]);
        }
        uint4 tg, tu;
        tg.x = tf32r(gv.x); tg.y = tf32r(gv.y); tg.z = tf32r(gv.z); tg.w = tf32r(gv.w);
        tu.x = tf32r(uv.x); tu.y = tf32r(uv.y); tu.z = tf32r(uv.z); tu.w = tf32r(uv.w);
        *(uint4*)&Bg[0][bk][bn] = tg;
        *(uint4*)&Bu[0][bk][bn] = tu;
    }
    __syncthreads();

    float ag[2][4][4] = {}, au[2][4][4] = {};
    const int NPAN = NH / 16;
    for (int p = 0; p < NPAN; p++) {
        int buf = p & 1;
        if (p + 1 < NPAN) {
            aptr += 16; wgp += (size_t)16 * NF; wup += (size_t)16 * NF;
            av0 = *(const float4*)(aptr);
            av1 = *(const float4*)(aptr + 4);
            gv  = *(const float4*)(wgp);
            uv  = *(const float4*)(wup);
        }
#pragma unroll
        for (int kk = 0; kk < 2; kk++) {
            int kb = kk * 8;
            unsigned a[2][4];
#pragma unroll
            for (int i = 0; i < 2; i++) {
                int rb = m0 + i * 16 + lq;
                a[i][0] = As[buf][kb + lr][rb];
                a[i][1] = As[buf][kb + lr][rb + 8];
                a[i][2] = As[buf][kb + lr + 4][rb];
                a[i][3] = As[buf][kb + lr + 4][rb + 8];
            }
#pragma unroll
            for (int j = 0; j < 4; j++) {
                int nn = n0 + j * 8 + lq;
                unsigned g0 = Bg[buf][kb + lr][nn];
                unsigned g1 = Bg[buf][kb + lr + 4][nn];
                unsigned u0 = Bu[buf][kb + lr][nn];
                unsigned u1 = Bu[buf][kb + lr + 4][nn];
#pragma unroll
                for (int i = 0; i < 2; i++) {
                    mma8(ag[i][j], a[i], g0, g1);
                    mma8(au[i][j], a[i], u0, u1);
                }
            }
        }
        if (p + 1 < NPAN) {
            int nb = buf ^ 1;
#pragma unroll
            for (int j = 0; j < 4; j++) {
                As[nb][ah * 8 + j][ar]     = tf32r(((const float*)&av0)[j]);
                As[nb][ah * 8 + 4 + j][ar] = tf32r(((const float*)&av1)[j]);
            }
            uint4 tg, tu;
            tg.x = tf32r(gv.x); tg.y = tf32r(gv.y); tg.z = tf32r(gv.z); tg.w = tf32r(gv.w);
            tu.x = tf32r(uv.x); tu.y = tf32r(uv.y); tu.z = tf32r(uv.z); tu.w = tf32r(uv.w);
            *(uint4*)&Bg[nb][bk][bn] = tg;
            *(uint4*)&Bu[nb][bk][bn] = tu;
        }
        __syncthreads();
    }

#pragma unroll
    for (int i = 0; i < 2; i++)
#pragma unroll
        for (int h = 0; h < 2; h++) {
            int rl = m0 + i * 16 + lq + h * 8;
            float* hp = g_sbuf + (size_t)(row0 + rl) * NF + nblk;
#pragma unroll
            for (int j = 0; j < 4; j++) {
                float x0 = silu(ag[i][j][h * 2])     * au[i][j][h * 2];
                float x1 = silu(ag[i][j][h * 2 + 1]) * au[i][j][h * 2 + 1];
                *(float2*)(hp + n0 + j * 8 + 2 * lr) = make_float2(x0, x1);
            }
        }
}

// ---------------- routed down GEMM: out += w * (hbuf @ Wd) ------------------
__global__ __launch_bounds__(256, 2) void moe_gemm2(const float* __restrict__ Wd,
                                                    float* __restrict__ out) {
    int e = blockIdx.z;
    int cnt = g_cnt[e]; if (cnt > NCAP) cnt = NCAP;
    int row0 = blockIdx.y * 128;
    if (row0 >= cnt) return;
    int nblk = blockIdx.x * 128;

    __shared__ unsigned As[2][16][136];
    __shared__ unsigned Bs[2][16][136];
    __shared__ int   stok[128];
    __shared__ float swgt[128];

    int tid = threadIdx.x;
    if (tid < 128) {
        int r = row0 + tid;
        stok[tid] = (r < cnt) ? g_tok[e * NCAP + r] : -1;
        swgt[tid] = (r < cnt) ? g_wgt[e * NCAP + r] : 0.f;
    }
    __syncthreads();

    const float* hb = g_hbuf + (size_t)e * NCAP * NF;
    const float* wd = Wd + (size_t)e * NF * NH;

    int ar = tid >> 1, ah = tid & 1;
    int bk = tid >> 4, bn = (tid & 15) * 8;
    const float* aptr = hb + (size_t)(row0 + ar) * NF + ah * 8;
    const float* bptr = wd + (size_t)bk * NH + nblk + bn;

    int lane = tid & 31, w = tid >> 5;
    int m0 = (w & 3) * 32, n0 = (w >> 2) * 64;
    int lq = lane >> 2, lr = lane & 3;

    float4 av0, av1, bv0, bv1;
    av0 = *(const float4*)(aptr);
    av1 = *(const float4*)(aptr + 4);
    bv0 = *(const float4*)(bptr);
    bv1 = *(const float4*)(bptr + 4);
    {
#pragma unroll
        for (int j = 0; j < 4; j++) {
            As[0][ah * 8 + j][ar]     = tf32r(((const float*)&av0)[j]);
            As[0][ah * 8 + 4 + j][ar] = tf32r(((const float*)&av1)[j]);
        }
        uint4 t0, t1;
        t0.x = tf32r(bv0.x); t0.y = tf32r(bv0.y); t0.z = tf32r(bv0.z); t0.w = tf32r(bv0.w);
        t1.x = tf32r(bv1.x); t1.y = tf32r(bv1.y); t1.z = tf32r(bv1.z); t1.w = tf32r(bv1.w);
        *(uint4*)&Bs[0][bk][bn]     = t0;
        *(uint4*)&Bs[0][bk][bn + 4] = t1;
    }
    __syncthreads();

    float acc[2][8][4] = {};
    const int NPAN = NF / 16;
    for (int p = 0; p < NPAN; p++) {
        int buf = p & 1;
        if (p + 1 < NPAN) {
            aptr += 16; bptr += (size_t)16 * NH;
            av0 = *(const float4*)(aptr);
            av1 = *(const float4*)(aptr + 4);
            bv0 = *(const float4*)(bptr);
            bv1 = *(const float4*)(bptr + 4);
        }
#pragma unroll
        for (int kk = 0; kk < 2; kk++) {
            int kb = kk * 8;
            unsigned a[2][4];
#pragma unroll
            for (int i = 0; i < 2; i++) {
                int rb = m0 + i * 16 + lq;
                a[i][0] = As[buf][kb + lr][rb];
                a[i][1] = As[buf][kb + lr][rb + 8];
                a[i][2] = As[buf][kb + lr + 4][rb];
                a[i][3] = As[buf][kb + lr + 4][rb + 8];
            }
#pragma unroll
            for (int j = 0; j < 8; j++) {
                int nn = n0 + j * 8 + lq;
                unsigned b0 = Bs[buf][kb + lr][nn];
                unsigned b1 = Bs[buf][kb + lr + 4][nn];
#pragma unroll
                for (int i = 0; i < 2; i++)
                    mma8(acc[i][j], a[i], b0, b1);
            }
        }
        if (p + 1 < NPAN) {
            int nb = buf ^ 1;
#pragma unroll
            for (int j = 0; j < 4; j++) {
                As[nb][ah * 8 + j][ar]     = tf32r(((const float*)&av0)[j]);
                As[nb][ah * 8 + 4 + j][ar] = tf32r(((const float*)&av1)[j]);
            }
            uint4 t0, t1;
            t0.x = tf32r(bv0.x); t0.y = tf32r(bv0.y); t0.z = tf32r(bv0.z); t0.w = tf32r(bv0.w);
            t1.x = tf32r(bv1.x); t1.y = tf32r(bv1.y); t1.z = tf32r(bv1.z); t1.w = tf32r(bv1.w);
            *(uint4*)&Bs[nb][bk][bn]     = t0;
            *(uint4*)&Bs[nb][bk][bn + 4] = t1;
        }
        __syncthreads();
    }

#pragma unroll
    for (int i = 0; i < 2; i++)
#pragma unroll
        for (int h = 0; h < 2; h++) {
            int rl = m0 + i * 16 + lq + h * 8;
            int tok = stok[rl];
            if (tok < 0) continue;
            float wt = swgt[rl];
            float* op = out + (size_t)tok * NH + nblk;
#pragma unroll
            for (int j = 0; j < 8; j++) {
                int col = n0 + j * 8 + 2 * lr;
                atomicAdd(op + col,     acc[i][j][h * 2]     * wt);
                atomicAdd(op + col + 1, acc[i][j][h * 2 + 1] * wt);
            }
        }
}

// ---------------- shared expert GEMM2: out = sbuf @ Wd (plain store) --------
__global__ __launch_bounds__(256, 2) void shared_gemm2(const float* __restrict__ Wd,
                                                       float* __restrict__ out) {
    int row0 = blockIdx.y * 128;
    int nblk = blockIdx.x * 128;

    __shared__ unsigned As[2][16][136];
    __shared__ unsigned Bs[2][16][136];

    int tid = threadIdx.x;
    int ar = tid >> 1, ah = tid & 1;
    int bk = tid >> 4, bn = (tid & 15) * 8;
    const float* aptr = g_sbuf + (size_t)(row0 + ar) * NF + ah * 8;
    const float* bptr = Wd + (size_t)bk * NH + nblk + bn;

    int lane = tid & 31, w = tid >> 5;
    int m0 = (w & 3) * 32, n0 = (w >> 2) * 64;
    int lq = lane >> 2, lr = lane & 3;

    float4 av0, av1, bv0, bv1;
    av0 = *(const float4*)(aptr);
    av1 = *(const float4*)(aptr + 4);
    bv0 = *(const float4*)(bptr);
    bv1 = *(const float4*)(bptr + 4);
    {
#pragma unroll
        for (int j = 0; j < 4; j++) {
            As[0][ah * 8 + j][ar]     = tf32r(((const float*)&av0)[j]);
            As[0][ah * 8 + 4 + j][ar] = tf32r(((const float*)&av1)[j]);
        }
        uint4 t0, t1;
        t0.x = tf32r(bv0.x); t0.y = tf32r(bv0.y); t0.z = tf32r(bv0.z); t0.w = tf32r(bv0.w);
        t1.x = tf32r(bv1.x); t1.y = tf32r(bv1.y); t1.z = tf32r(bv1.z); t1.w = tf32r(bv1.w);
        *(uint4*)&Bs[0][bk][bn]     = t0;
        *(uint4*)&Bs[0][bk][bn + 4] = t1;
    }
    __syncthreads();

    float acc[2][8][4] = {};
    const int NPAN = NF / 16;
    for (int p = 0; p < NPAN; p++) {
        int buf = p & 1;
        if (p + 1 < NPAN) {
            aptr += 16; bptr += (size_t)16 * NH;
            av0 = *(const float4*)(aptr);
            av1 = *(const float4*)(aptr + 4);
            bv0 = *(const float4*)(bptr);
            bv1 = *(const float4*)(bptr + 4);
        }
#pragma unroll
        for (int kk = 0; kk < 2; kk++) {
            int kb = kk * 8;
            unsigned a[2][4];
#pragma unroll
            for (int i = 0; i < 2; i++) {
                int rb = m0 + i * 16 + lq;
                a[i][0] = As[buf][kb + lr][rb];
                a[i][1] = As[buf][kb + lr][rb + 8];
                a[i][2] = As[buf][kb + lr + 4][rb];
                a[i][3] = As[buf][kb + lr + 4][rb + 8];
            }
#pragma unroll
            for (int j = 0; j < 8; j++) {
                int nn = n0 + j * 8 + lq;
                unsigned b0 = Bs[buf][kb + lr][nn];
                unsigned b1 = Bs[buf][kb + lr + 4][nn];
#pragma unroll
                for (int i = 0; i < 2; i++)
                    mma8(acc[i][j], a[i], b0, b1);
            }
        }
        if (p + 1 < NPAN) {
            int nb = buf ^ 1;
#pragma unroll
            for (int j = 0; j < 4; j++) {
                As[nb][ah * 8 + j][ar]     = tf32r(((const float*)&av0)[j]);
                As[nb][ah * 8 + 4 + j][ar] = tf32r(((const float*)&av1)[j]);
            }
            uint4 t0, t1;
            t0.x = tf32r(bv0.x); t0.y = tf32r(bv0.y); t0.z = tf32r(bv0.z); t0.w = tf32r(bv0.w);
            t1.x = tf32r(bv1.x); t1.y = tf32r(bv1.y); t1.z = tf32r(bv1.z); t1.w = tf32r(bv1.w);
            *(uint4*)&Bs[nb][bk][bn]     = t0;
            *(uint4*)&Bs[nb][bk][bn + 4] = t1;
        }
        __syncthreads();
    }

#pragma unroll
    for (int i = 0; i < 2; i++)
#pragma unroll
        for (int h = 0; h < 2; h++) {
            int rl = row0 + m0 + i * 16 + lq + h * 8;
            float* op = out + (size_t)rl * NH + nblk;
#pragma unroll
            for (int j = 0; j < 8; j++) {
                int col = n0 + j * 8 + 2 * lr;
                *(float2*)(op + col) =
                    make_float2(acc[i][j][h * 2], acc[i][j][h * 2 + 1]);
            }
        }
}

// ---------------------------------------------------------------------------
extern "C" void kernel_launch(void* const* d_in, const int* in_sizes, int n_in,
                              void* d_out, int out_size) {
    const float* x       = (const float*)d_in[0];
    const float* gate_w  = (const float*)d_in[1];
    const float* bias    = (const float*)d_in[2];
    const float* w_gate  = (const float*)d_in[3];
    const float* w_up    = (const float*)d_in[4];
    const float* w_down  = (const float*)d_in[5];
    const float* ws_gate = (const float*)d_in[6];
    const float* ws_up   = (const float*)d_in[7];
    const float* ws_down = (const float*)d_in[8];
    float* out = (float*)d_out;

    zero_cnt_kernel<<<1, 64>>>();
    router_gemm<<<NT / 64, 256>>>(x, gate_w);
    topk_route<<<NT / 256, 256>>>(bias);

    // shared expert first: plain stores initialize the (poisoned) output
    shared_gemm1<<<dim3(NF / 64, NT / 128), 256>>>(x, ws_gate, ws_up);
    shared_gemm2<<<dim3(NH / 128, NT / 128), 256>>>(ws_down, out);

    // routed experts: grouped GEMMs, weighted atomic accumulation into out
    moe_gemm1<<<dim3(NF / 64, NCAP / 128, NE), 256>>>(x, w_gate, w_up);
    moe_gemm2<<<dim3(NH / 128, NCAP / 128, NE), 256>>>(w_down, out);
}